// round 7
// baseline (speedup 1.0000x reference)
#include <cuda_runtime.h>
#include <math.h>
#include <stdint.h>

// tcgen05 is an architecture-specific feature: only emit it in the sm_103a/sm_100a
// compilation passes. Non-'a' passes get an empty stub body.
#if defined(__CUDA_ARCH_FEAT_SM103_ALL) || defined(__CUDA_ARCH_FEAT_SM100_ALL) || defined(__CUDA_ARCH_FEAT_SM101_ALL) || defined(__CUDA_ARCH_FEAT_SM110_ALL)
#define HAS_TC 1
#else
#define HAS_TC 0
#endif

// Problem dims
constexpr int Bd = 8;
constexpr int Sd = 1024;
constexpr int Ed = 1024;
constexpr int Fd = 4096;
constexpr int MTOT = Bd * Sd;   // 8192

// cg2 GEMM tile config: 2-CTA pair computes a 256x512 super-tile.
// Per CTA per stage: A 128 rows (M split) + B 256 rows (N split, 2 groups of 128).
constexpr int TMM = 256;        // M per pair (M_atom=256, cta_group::2)
constexpr int TNN = 512;        // N per pair (2 x N=256 dispatches)
constexpr int TK = 32;          // K elems per stage (128B per row)
constexpr int NS = 4;           // pipeline stages
constexpr int STAGE_BYTES = (128 + 256) * 128;          // 49152 per CTA
constexpr int SMEM_TOTAL = 1024 + NS * STAGE_BYTES;     // 197632

// idesc: c=F32(1), a=TF32(2), b=TF32(2), K-major both, N=256, M=256 (cg2 total M)
constexpr uint32_t IDESC =
    (1u << 4) | (2u << 7) | (2u << 10) | ((256 / 8) << 17) | ((TMM / 16) << 24);

#define OFF_TMEM   0
#define OFF_FULL(s)  (8 + 8*(s))
#define OFF_EMPTY(s) (8 + 8*NS + 8*(s))
#define OFF_FIN      (8 + 16*NS)

// ---------------- scratch (device globals) ---------------------------------
__device__ float g_xr  [(long long)MTOT * Ed];
__device__ float g_qk  [(long long)2 * MTOT * Ed];   // q | k contiguous
__device__ float g_vt  [(long long)MTOT * Ed];       // V transposed [E,S] per batch
__device__ float g_at  [(long long)Bd * Sd * Sd];
__device__ float g_ao  [(long long)MTOT * Ed];
__device__ float g_tmp [(long long)MTOT * Ed];
__device__ float g_h1  [(long long)MTOT * Ed];
__device__ float g_ff  [(long long)MTOT * Fd];
__device__ float g_wt  [(long long)3 * Ed * Ed];     // Wq^T | Wk^T | Wv^T
__device__ float g_b2  [2 * Ed];
__device__ float g_wdt [(long long)Ed * Ed];
__device__ float g_wit [(long long)Fd * Ed];
__device__ float g_wot [(long long)Ed * Fd];

// ---------------- PTX helpers -------------------------------------------------
__device__ __forceinline__ uint32_t smem_u32(const void* p) {
    uint32_t a;
    asm("{ .reg .u64 t; cvta.to.shared.u64 t, %1; cvt.u32.u64 %0, t; }" : "=r"(a) : "l"(p));
    return a;
}
__device__ __forceinline__ uint32_t elect_one() {
    uint32_t p;
    asm volatile("{ .reg .pred p; elect.sync _|p, 0xFFFFFFFF; selp.b32 %0,1,0,p; }" : "=r"(p));
    return p;
}
__device__ __forceinline__ uint32_t ctarank() {
    uint32_t r;
    asm("mov.u32 %0, %%cluster_ctarank;" : "=r"(r));
    return r;
}
__device__ __forceinline__ void cluster_sync() {
    asm volatile("barrier.cluster.arrive.aligned;" ::: "memory");
    asm volatile("barrier.cluster.wait.aligned;" ::: "memory");
}
__device__ __forceinline__ void mbar_init(uint32_t a, uint32_t c) {
    asm volatile("mbarrier.init.shared.b64 [%0], %1;" :: "r"(a), "r"(c) : "memory");
}
// Arrive on the mbarrier at the same offset in cluster CTA `rank` (cross-CTA safe).
__device__ __forceinline__ void mbar_arrive_cluster(uint32_t a, uint32_t rank) {
    asm volatile(
        "{\n\t.reg .b32 ra;\n\t"
        "mapa.shared::cluster.u32 ra, %0, %1;\n\t"
        "mbarrier.arrive.shared::cluster.b64 _, [ra];\n\t}"
        :: "r"(a), "r"(rank) : "memory");
}
// Local wait, cta-scope acquire.
__device__ __forceinline__ void mbar_wait(uint32_t a, uint32_t ph) {
    uint32_t done;
    asm volatile(
        "{\n\t.reg .pred p;\n\t"
        "mbarrier.try_wait.parity.acquire.cta.shared::cta.b64 p, [%1], %2;\n\t"
        "selp.b32 %0, 1, 0, p;\n\t}"
        : "=r"(done) : "r"(a), "r"(ph) : "memory");
    if (!done) {
        asm volatile(
            "{\n\t.reg .pred P1;\n\t"
            "WL%=:\n\t"
            "mbarrier.try_wait.parity.acquire.cta.shared::cta.b64 P1, [%0], %1, 0x989680;\n\t"
            "@P1 bra.uni WD%=;\n\t"
            "bra.uni WL%=;\n\t"
            "WD%=:\n\t}"
            :: "r"(a), "r"(ph) : "memory");
    }
}
// Local wait, cluster-scope acquire (synchronizes-with peer-CTA release arrives).
__device__ __forceinline__ void mbar_wait_cl(uint32_t a, uint32_t ph) {
    uint32_t done;
    asm volatile(
        "{\n\t.reg .pred p;\n\t"
        "mbarrier.try_wait.parity.acquire.cluster.shared::cta.b64 p, [%1], %2;\n\t"
        "selp.b32 %0, 1, 0, p;\n\t}"
        : "=r"(done) : "r"(a), "r"(ph) : "memory");
    if (!done) {
        asm volatile(
            "{\n\t.reg .pred P1;\n\t"
            "WL%=:\n\t"
            "mbarrier.try_wait.parity.acquire.cluster.shared::cta.b64 P1, [%0], %1, 0x989680;\n\t"
            "@P1 bra.uni WD%=;\n\t"
            "bra.uni WL%=;\n\t"
            "WD%=:\n\t}"
            :: "r"(a), "r"(ph) : "memory");
    }
}
__device__ __forceinline__ void cp16(uint32_t dst, const void* src) {
    asm volatile("cp.async.cg.shared.global [%0], [%1], 16;" :: "r"(dst), "l"(src) : "memory");
}
__device__ __forceinline__ uint64_t make_desc(uint32_t addr) {
    // SW128, version=1 (Blackwell), SBO=64, LBO=1
    return 0x4000404000010000ULL | ((uint64_t)(addr >> 4) & 0x3FFF);
}
__device__ __forceinline__ float rna_tf32(float x) {
    uint32_t u;
    asm("cvt.rna.tf32.f32 %0, %1;" : "=r"(u) : "f"(x));
    return __uint_as_float(u);
}

#if HAS_TC
__device__ __forceinline__ void mma_tf32_cg2(uint32_t d, uint64_t ad, uint64_t bd,
                                             uint32_t idesc, uint32_t en) {
    asm volatile(
        "{\n\t.reg .pred p;\n\t"
        "setp.ne.u32 p, %4, 0;\n\t"
        "tcgen05.mma.cta_group::2.kind::tf32 [%0], %1, %2, %3, "
        "{%5, %5, %5, %5, %5, %5, %5, %5}, p;\n\t}"
        :: "r"(d), "l"(ad), "l"(bd), "r"(idesc), "r"(en), "r"(0u)
        : "memory");
}
#define TC_ALLOC_CG2(sa, n)  asm volatile("tcgen05.alloc.cta_group::2.sync.aligned.shared::cta.b32 [%0], %1;" :: "r"(sa), "r"(n) : "memory")
#define TC_DEALLOC_CG2(t, n) asm volatile("tcgen05.dealloc.cta_group::2.sync.aligned.b32 %0, %1;" :: "r"(t), "r"(n))
#define TC_RELINQ_CG2()      asm volatile("tcgen05.relinquish_alloc_permit.cta_group::2.sync.aligned;")
#define TC_COMMIT_MC_CG2(mb) asm volatile("tcgen05.commit.cta_group::2.mbarrier::arrive::one.shared::cluster.multicast::cluster.b64 [%0], %1;" :: "r"(mb), "h"((uint16_t)0x3) : "memory")
#define TC_FENCE_AFTER()     asm volatile("tcgen05.fence::after_thread_sync;" ::: "memory")
#define TC_WAIT_LD()         asm volatile("tcgen05.wait::ld.sync.aligned;" ::: "memory")

#define LDTM_X32(r, ta) \
    asm volatile( \
        "tcgen05.ld.sync.aligned.32x32b.x32.b32 " \
        "{%0, %1, %2, %3, %4, %5, %6, %7, " \
        " %8, %9, %10, %11, %12, %13, %14, %15, " \
        " %16, %17, %18, %19, %20, %21, %22, %23, " \
        " %24, %25, %26, %27, %28, %29, %30, %31}, [%32];" \
        : "=r"((r)[0]),  "=r"((r)[1]),  "=r"((r)[2]),  "=r"((r)[3]), \
          "=r"((r)[4]),  "=r"((r)[5]),  "=r"((r)[6]),  "=r"((r)[7]), \
          "=r"((r)[8]),  "=r"((r)[9]),  "=r"((r)[10]), "=r"((r)[11]), \
          "=r"((r)[12]), "=r"((r)[13]), "=r"((r)[14]), "=r"((r)[15]), \
          "=r"((r)[16]), "=r"((r)[17]), "=r"((r)[18]), "=r"((r)[19]), \
          "=r"((r)[20]), "=r"((r)[21]), "=r"((r)[22]), "=r"((r)[23]), \
          "=r"((r)[24]), "=r"((r)[25]), "=r"((r)[26]), "=r"((r)[27]), \
          "=r"((r)[28]), "=r"((r)[29]), "=r"((r)[30]), "=r"((r)[31]) \
        : "r"(ta))
#endif // HAS_TC

// ---------------- cg2 tcgen05 TF32 GEMM (256x512 super-tile per pair) ----------
// C = act(alpha * A @ Bt^T + bias + resid), A [M,K] K-major, Bt [N,K] K-major.
// Cluster of 2 CTAs: rank r holds A rows [bm + r*128, +128) and, for each N-group
// j in {0,1}, B rows [bn + j*256 + r*128, +128). Leader issues 2 N-group MMA
// dispatches per K-step into TMEM cols [0,256) and [256,512). Each CTA's TMEM
// holds its own 128 M-rows x 512 cols of D.
// BROW: bias indexed by output ROW (for V^T); else by column.
template<int ACT, bool ROUND, bool BROW>
__global__ void __launch_bounds__(160, 1) __cluster_dims__(2, 1, 1)
tc_gemm(const float* __restrict__ A, const float* __restrict__ Bt,
        const float* __restrict__ bias, const float* __restrict__ resid,
        float* __restrict__ C, int K, int N, float alpha,
        long long sA, long long sB, long long sC, long long sBias)
{
#if HAS_TC
    extern __shared__ char smem[];
    const uint32_t sb = smem_u32(smem);
    const int tid = threadIdx.x;
    const int wid = tid >> 5;
    const uint32_t rank = ctarank();

    A    += blockIdx.z * sA;
    Bt   += blockIdx.z * sB;
    C    += blockIdx.z * sC;
    if (bias) bias += blockIdx.z * sBias;
    const int bm = blockIdx.y * TMM;
    const int bn = (blockIdx.x >> 1) * TNN;
    const int nk = K / TK;

    if (tid == 0) {
        for (int s = 0; s < NS; s++) {
            mbar_init(sb + OFF_FULL(s), 256);   // 128 producer threads x 2 CTAs
            mbar_init(sb + OFF_EMPTY(s), 1);
        }
        mbar_init(sb + OFF_FIN, 1);
    }
    if (wid == 4) {
        TC_ALLOC_CG2(sb + OFF_TMEM, 512);
        TC_RELINQ_CG2();
    }
    __syncthreads();
    uint32_t tmem;
    asm volatile("ld.shared.b32 %0, [%1];" : "=r"(tmem) : "r"(sb + OFF_TMEM));

    // All mbarriers must be initialized cluster-wide before any cross-CTA
    // arrive or peer-smem MMA read.
    cluster_sync();

    if (tid < 128) {
        // ---- producer: coalesced cp.async, 24 x 16B per thread per stage ----
        // a = tid>>3 (row phase 0..15), c = tid&7 (16B chunk). Rows a+16m, m=0..7
        // within each 128-row panel (A; B group 0; B group 1).
        const int a = tid >> 3;
        const int c = tid & 7;
        const float* pA  = A  + (long long)(bm + rank * 128 + a) * K + c * 4;
        const float* pB0 = Bt + (long long)(bn + rank * 128 + a) * K + c * 4;
        const float* pB1 = Bt + (long long)(bn + 256 + rank * 128 + a) * K + c * 4;
        uint32_t o0 = (uint32_t)(a * 128 + c * 16);
        const uint32_t swA = o0 ^ ((o0 >> 3) & 0x70);   // row bits 0-2 = a&7, invariant in m
        const long long str16 = 16LL * K;

        int s = 0; uint32_t eph = 1;
        for (int kt = 0; kt < nk; kt++) {
            mbar_wait(sb + OFF_EMPTY(s), eph);
            const uint32_t st = sb + 1024 + s * STAGE_BYTES;
            #pragma unroll
            for (int m = 0; m < 8; m++)
                cp16(st + swA + m * 2048, pA + m * str16);
            #pragma unroll
            for (int m = 0; m < 8; m++)
                cp16(st + swA + 16384 + m * 2048, pB0 + m * str16);
            #pragma unroll
            for (int m = 0; m < 8; m++)
                cp16(st + swA + 32768 + m * 2048, pB1 + m * str16);
            asm volatile("cp.async.commit_group;" ::: "memory");
            pA += TK; pB0 += TK; pB1 += TK;
            if (kt >= NS - 1) {
                asm volatile("cp.async.wait_group %0;" :: "n"(NS - 1) : "memory");
                asm volatile("fence.proxy.async;" ::: "memory");
                mbar_arrive_cluster(sb + OFF_FULL((kt - (NS - 1)) % NS), 0);
            }
            if (++s == NS) { s = 0; eph ^= 1; }
        }
        asm volatile("cp.async.wait_group 0;" ::: "memory");
        asm volatile("fence.proxy.async;" ::: "memory");
        for (int j = nk - (NS - 1); j < nk; j++)
            mbar_arrive_cluster(sb + OFF_FULL(j % NS), 0);

        // ---- epilogue: this CTA's 128 rows x 512 cols from local TMEM ----
        mbar_wait(sb + OFF_FIN, 0);
        TC_FENCE_AFTER();
        const int lane = tid & 31;
        const long long row = bm + rank * 128 + (tid >> 5) * 32 + lane;
        float* crow = C + row * (long long)N + bn;
        const float* rrow = resid ? resid + row * (long long)N + bn : nullptr;
        float brow = 0.0f;
        if (BROW && bias) brow = bias[row];

        #pragma unroll 1
        for (int cb = 0; cb < 16; cb++) {
            uint32_t r[32];
            LDTM_X32(r, tmem + cb * 32);
            TC_WAIT_LD();
            float v[32];
            #pragma unroll
            for (int j = 0; j < 32; j++) v[j] = __uint_as_float(r[j]) * alpha;
            if (bias) {
                if (BROW) {
                    #pragma unroll
                    for (int j = 0; j < 32; j++) v[j] += brow;
                } else {
                    #pragma unroll
                    for (int j0 = 0; j0 < 32; j0 += 4) {
                        float4 bb = *reinterpret_cast<const float4*>(bias + bn + cb * 32 + j0);
                        v[j0+0] += bb.x; v[j0+1] += bb.y; v[j0+2] += bb.z; v[j0+3] += bb.w;
                    }
                }
            }
            if (rrow) {
                #pragma unroll
                for (int j0 = 0; j0 < 32; j0 += 4) {
                    float4 rv = *reinterpret_cast<const float4*>(rrow + cb * 32 + j0);
                    v[j0+0] += rv.x; v[j0+1] += rv.y; v[j0+2] += rv.z; v[j0+3] += rv.w;
                }
            }
            if constexpr (ACT == 1) {
                #pragma unroll
                for (int j = 0; j < 32; j++)
                    v[j] = 0.5f * v[j] * (1.0f + erff(v[j] * 0.70710678118654752f));
            }
            if constexpr (ROUND) {
                #pragma unroll
                for (int j = 0; j < 32; j++) v[j] = rna_tf32(v[j]);
            }
            #pragma unroll
            for (int j0 = 0; j0 < 32; j0 += 4) {
                float4 o; o.x = v[j0]; o.y = v[j0+1]; o.z = v[j0+2]; o.w = v[j0+3];
                *reinterpret_cast<float4*>(crow + cb * 32 + j0) = o;
            }
        }
    } else if (rank == 0) {
        // ---- leader warp 4: MMA issuer (2 N-group dispatches per K-step) ----
        uint32_t ep = elect_one();
        int s = 0; uint32_t ph = 0;
        for (int kt = 0; kt < nk; kt++) {
            mbar_wait_cl(sb + OFF_FULL(s), ph);
            if (ep) {
                const uint32_t st = sb + 1024 + s * STAGE_BYTES;
                uint64_t ad  = make_desc(st);
                uint64_t bd0 = make_desc(st + 16384);
                uint64_t bd1 = make_desc(st + 32768);
                const uint32_t en0 = (uint32_t)(kt != 0);
                #pragma unroll
                for (int j = 0; j < 4; j++) {
                    const uint32_t en = en0 | (uint32_t)(j != 0);
                    mma_tf32_cg2(tmem,       ad + 2 * j, bd0 + 2 * j, IDESC, en);
                    mma_tf32_cg2(tmem + 256, ad + 2 * j, bd1 + 2 * j, IDESC, en);
                }
                if (kt == nk - 1) TC_COMMIT_MC_CG2(sb + OFF_FIN);
                else              TC_COMMIT_MC_CG2(sb + OFF_EMPTY(s));
            }
            if (++s == NS) { s = 0; ph ^= 1; }
        }
    }

    __syncthreads();
    if (wid == 4) TC_DEALLOC_CG2(tmem, 512);
    // No CTA may exit while its peer may still arrive on / read this CTA's smem.
    cluster_sync();
#endif // HAS_TC
}

// ---------------- elementwise kernels ---------------------------------------
__device__ __forceinline__ float block_sum(float v, float* sh) {
    const int lane = threadIdx.x & 31, w = threadIdx.x >> 5;
    #pragma unroll
    for (int o = 16; o; o >>= 1) v += __shfl_xor_sync(0xffffffffu, v, o);
    __syncthreads();
    if (lane == 0) sh[w] = v;
    __syncthreads();
    float s = 0.f;
    #pragma unroll
    for (int i = 0; i < 8; i++) s += sh[i];
    return s;
}
__device__ __forceinline__ float block_max(float v, float* sh) {
    const int lane = threadIdx.x & 31, w = threadIdx.x >> 5;
    #pragma unroll
    for (int o = 16; o; o >>= 1) v = fmaxf(v, __shfl_xor_sync(0xffffffffu, v, o));
    __syncthreads();
    if (lane == 0) sh[w] = v;
    __syncthreads();
    float s = -INFINITY;
    #pragma unroll
    for (int i = 0; i < 8; i++) s = fmaxf(s, sh[i]);
    return s;
}

__global__ void __launch_bounds__(256) softmax_kernel(float* __restrict__ data)
{
    __shared__ float sh[8];
    const long long row = blockIdx.x;
    float4* p = reinterpret_cast<float4*>(data + row * 1024);
    float4 x = p[threadIdx.x];
    float m = fmaxf(fmaxf(x.x, x.y), fmaxf(x.z, x.w));
    m = block_max(m, sh);
    x.x = expf(x.x - m); x.y = expf(x.y - m);
    x.z = expf(x.z - m); x.w = expf(x.w - m);
    float s = x.x + x.y + x.z + x.w;
    s = block_sum(s, sh);
    const float inv = 1.0f / s;
    x.x = rna_tf32(x.x * inv); x.y = rna_tf32(x.y * inv);
    x.z = rna_tf32(x.z * inv); x.w = rna_tf32(x.w * inv);
    p[threadIdx.x] = x;
}

template<bool ROUND>
__global__ void __launch_bounds__(256)
ln_kernel(const float* __restrict__ in, const float* __restrict__ g,
          const float* __restrict__ b, float* __restrict__ out)
{
    __shared__ float sh[8];
    const long long row = blockIdx.x;
    const float4* p = reinterpret_cast<const float4*>(in + row * 1024);
    float4 x = p[threadIdx.x];
    float s = x.x + x.y + x.z + x.w;
    s = block_sum(s, sh);
    const float mu = s * (1.0f / 1024.0f);
    const float dx = x.x - mu, dy = x.y - mu, dz = x.z - mu, dw = x.w - mu;
    float ss = dx * dx + dy * dy + dz * dz + dw * dw;
    ss = block_sum(ss, sh);
    const float rstd = rsqrtf(ss * (1.0f / 1024.0f) + 1e-12f);
    const float4 gg = reinterpret_cast<const float4*>(g)[threadIdx.x];
    const float4 bb = reinterpret_cast<const float4*>(b)[threadIdx.x];
    float4 o;
    o.x = dx * rstd * gg.x + bb.x;
    o.y = dy * rstd * gg.y + bb.y;
    o.z = dz * rstd * gg.z + bb.z;
    o.w = dw * rstd * gg.w + bb.w;
    if (ROUND) { o.x = rna_tf32(o.x); o.y = rna_tf32(o.y); o.z = rna_tf32(o.z); o.w = rna_tf32(o.w); }
    reinterpret_cast<float4*>(out + row * 1024)[threadIdx.x] = o;
}

// Fast 64x64 transpose: out[c, r] = (rna) in[r, c]; batched via z.
// in is [R, C]; launch grid = (C/64, R/64, batch).
template<bool ROUND>
__global__ void __launch_bounds__(256)
transpose_fast(const float* __restrict__ in, float* __restrict__ out,
               int R, int C, long long sIn, long long sOut)
{
    __shared__ float t[64][65];
    in  += blockIdx.z * sIn;
    out += blockIdx.z * sOut;
    const int r0 = blockIdx.y * 64, c0 = blockIdx.x * 64;
    const int fc = (threadIdx.x & 15) * 4;   // 0..60
    const int fr = threadIdx.x >> 4;         // 0..15

    #pragma unroll
    for (int i = 0; i < 4; i++) {
        const int r = fr + i * 16;
        float4 x = *reinterpret_cast<const float4*>(in + (long long)(r0 + r) * C + c0 + fc);
        t[fc + 0][r] = x.x; t[fc + 1][r] = x.y; t[fc + 2][r] = x.z; t[fc + 3][r] = x.w;
    }
    __syncthreads();
    #pragma unroll
    for (int i = 0; i < 4; i++) {
        const int oc = fr + i * 16;
        float4 y;
        y.x = t[oc][fc + 0]; y.y = t[oc][fc + 1];
        y.z = t[oc][fc + 2]; y.w = t[oc][fc + 3];
        if (ROUND) {
            y.x = rna_tf32(y.x); y.y = rna_tf32(y.y);
            y.z = rna_tf32(y.z); y.w = rna_tf32(y.w);
        }
        *reinterpret_cast<float4*>(out + (long long)(c0 + oc) * R + r0 + fc) = y;
    }
}

// Blocks 0..255: grid-stride RNA-round of x into xr.
// Blocks 256/257: copy bq/bk into the concatenated b2 buffer (no rounding).
__global__ void __launch_bounds__(256)
round_bias_kernel(const float4* __restrict__ in, float4* __restrict__ out, long long n4,
                  const float4* __restrict__ bq, const float4* __restrict__ bk,
                  float4* __restrict__ b2)
{
    if (blockIdx.x >= 256) {
        const float4* src = (blockIdx.x == 256) ? bq : bk;
        b2[(blockIdx.x - 256) * 256 + threadIdx.x] = src[threadIdx.x];
        return;
    }
    for (long long i = blockIdx.x * 256LL + threadIdx.x; i < n4; i += 256LL * 256LL) {
        float4 v = in[i];
        v.x = rna_tf32(v.x); v.y = rna_tf32(v.y);
        v.z = rna_tf32(v.z); v.w = rna_tf32(v.w);
        out[i] = v;
    }
}

// ---------------- host launcher -----------------------------------------------
extern "C" void kernel_launch(void* const* d_in, const int* in_sizes, int n_in,
                              void* d_out, int out_size)
{
    const float* x  = (const float*)d_in[0];
    const float* Wq = (const float*)d_in[1];
    const float* bq = (const float*)d_in[2];
    const float* Wk = (const float*)d_in[3];
    const float* bk = (const float*)d_in[4];
    const float* Wv = (const float*)d_in[5];
    const float* bv = (const float*)d_in[6];
    const float* Wd = (const float*)d_in[7];
    const float* bd = (const float*)d_in[8];
    const float* g1 = (const float*)d_in[9];
    const float* b1 = (const float*)d_in[10];
    const float* Wi = (const float*)d_in[11];
    const float* bi = (const float*)d_in[12];
    const float* Wo = (const float*)d_in[13];
    const float* bo = (const float*)d_in[14];
    const float* g2 = (const float*)d_in[15];
    const float* b2 = (const float*)d_in[16];
    float* out = (float*)d_out;

    float *xr, *qk, *vt, *at, *ao, *tmp, *h1, *ff;
    float *wt, *b2qk, *wdt, *wit, *wot;
    cudaGetSymbolAddress((void**)&xr,   g_xr);
    cudaGetSymbolAddress((void**)&qk,   g_qk);
    cudaGetSymbolAddress((void**)&vt,   g_vt);
    cudaGetSymbolAddress((void**)&at,   g_at);
    cudaGetSymbolAddress((void**)&ao,   g_ao);
    cudaGetSymbolAddress((void**)&tmp,  g_tmp);
    cudaGetSymbolAddress((void**)&h1,   g_h1);
    cudaGetSymbolAddress((void**)&ff,   g_ff);
    cudaGetSymbolAddress((void**)&wt,   g_wt);
    cudaGetSymbolAddress((void**)&b2qk, g_b2);
    cudaGetSymbolAddress((void**)&wdt,  g_wdt);
    cudaGetSymbolAddress((void**)&wit,  g_wit);
    cudaGetSymbolAddress((void**)&wot,  g_wot);

    cudaFuncSetAttribute(tc_gemm<0, true,  false>, cudaFuncAttributeMaxDynamicSharedMemorySize, SMEM_TOTAL);
    cudaFuncSetAttribute(tc_gemm<0, true,  true >, cudaFuncAttributeMaxDynamicSharedMemorySize, SMEM_TOTAL);
    cudaFuncSetAttribute(tc_gemm<0, false, false>, cudaFuncAttributeMaxDynamicSharedMemorySize, SMEM_TOTAL);
    cudaFuncSetAttribute(tc_gemm<1, true,  false>, cudaFuncAttributeMaxDynamicSharedMemorySize, SMEM_TOTAL);

    const long long ME = (long long)MTOT * Ed;
    const long long SE = (long long)Sd * Ed;
    const long long SS = (long long)Sd * Sd;
    const long long EE = (long long)Ed * Ed;
    float* q = qk;
    float* k = qk + ME;
    const dim3 tb(256);
    const dim3 gt(160);

    // GEMM grids: x = N/256 (pairs of CTAs per 512-wide super-tile), y = M/256.
    // 0: round x -> xr and build [bq|bk]
    round_bias_kernel<<<258, tb>>>((const float4*)x, (float4*)xr, ME / 4,
                                   (const float4*)bq, (const float4*)bk, (float4*)b2qk);
    // 1-2: Wq/Wk transposes
    transpose_fast<true><<<dim3(Ed/64, Ed/64, 1), tb>>>(Wq, wt,      Ed, Ed, 0, 0);
    transpose_fast<true><<<dim3(Ed/64, Ed/64, 1), tb>>>(Wk, wt + EE, Ed, Ed, 0, 0);
    // 3: fused Q,K projections  <-- profiled launch (harness offset 2 + idx 3 = ncu -s 5)
    tc_gemm<0, true, false><<<dim3(Ed/256, MTOT/TMM, 2), gt, SMEM_TOTAL>>>(
        xr, wt, b2qk, nullptr, qk, Ed, Ed, 1.0f, 0, EE, ME, Ed);
    // 4: Wv transpose
    transpose_fast<true><<<dim3(Ed/64, Ed/64, 1), tb>>>(Wv, wt + 2 * EE, Ed, Ed, 0, 0);
    // 5: vt = Wv^T @ x^T + bv (per batch) -> [E, S], row-bias epilogue
    tc_gemm<0, true, true><<<dim3(Sd/256, Ed/TMM, Bd), gt, SMEM_TOTAL>>>(
        wt + 2 * EE, xr, bv, nullptr, vt, Ed, Sd, 1.0f, 0, SE, SE, 0);
    // 6: scores = q @ k^T / 32
    tc_gemm<0, false, false><<<dim3(Sd/256, Sd/TMM, Bd), gt, SMEM_TOTAL>>>(
        q, k, nullptr, nullptr, at, Ed, Sd, 0.03125f, SE, SE, SS, 0);
    // 7: softmax (RNA-rounded)
    softmax_kernel<<<Bd * Sd, tb>>>(at);
    // 8: attn_out = attn_w @ v (Bt = vt, [E,S] K-major)
    tc_gemm<0, true, false><<<dim3(Ed/256, Sd/TMM, Bd), gt, SMEM_TOTAL>>>(
        at, vt, nullptr, nullptr, ao, Sd, Ed, 1.0f, SS, SE, SE, 0);
    // 9-11: Wd GEMM (+bias +resid x) then LN1
    transpose_fast<true><<<dim3(Ed/64, Ed/64, 1), tb>>>(Wd, wdt, Ed, Ed, 0, 0);
    tc_gemm<0, false, false><<<dim3(Ed/256, MTOT/TMM, 1), gt, SMEM_TOTAL>>>(
        ao, wdt, bd, x, tmp, Ed, Ed, 1.0f, 0, 0, 0, 0);
    ln_kernel<true><<<MTOT, tb>>>(tmp, g1, b1, h1);
    // 12-13: ff = gelu(h1 @ Wi + bi). Wi is [Ed, Fd] -> grid (Fd/64, Ed/64).
    transpose_fast<true><<<dim3(Fd/64, Ed/64, 1), tb>>>(Wi, wit, Ed, Fd, 0, 0);
    tc_gemm<1, true, false><<<dim3(Fd/256, MTOT/TMM, 1), gt, SMEM_TOTAL>>>(
        h1, wit, bi, nullptr, ff, Ed, Fd, 1.0f, 0, 0, 0, 0);
    // 14-16: out = LN(ff @ Wo + bo + h1). Wo is [Fd, Ed] -> grid (Ed/64, Fd/64).
    transpose_fast<true><<<dim3(Ed/64, Fd/64, 1), tb>>>(Wo, wot, Fd, Ed, 0, 0);
    tc_gemm<0, false, false><<<dim3(Ed/256, MTOT/TMM, 1), gt, SMEM_TOTAL>>>(
        ff, wot, bo, h1, tmp, Fd, Ed, 1.0f, 0, 0, 0, 0);
    ln_kernel<false><<<MTOT, tb>>>(tmp, g2, b2, out);
}

// round 8
// speedup vs baseline: 1.5997x; 1.5997x over previous
#include <cuda_runtime.h>
#include <math.h>
#include <stdint.h>

// tcgen05 is an architecture-specific feature: only emit it in the sm_103a/sm_100a
// compilation passes. Non-'a' passes get an empty stub body.
#if defined(__CUDA_ARCH_FEAT_SM103_ALL) || defined(__CUDA_ARCH_FEAT_SM100_ALL) || defined(__CUDA_ARCH_FEAT_SM101_ALL) || defined(__CUDA_ARCH_FEAT_SM110_ALL)
#define HAS_TC 1
#else
#define HAS_TC 0
#endif

// Problem dims
constexpr int Bd = 8;
constexpr int Sd = 1024;
constexpr int Ed = 1024;
constexpr int Fd = 4096;
constexpr int MTOT = Bd * Sd;   // 8192

// tcgen05 GEMM tile config: 256x256 tile = 2 x (128x256) MMA into TMEM halves
constexpr int TMM = 256;        // M per CTA (two 128-row MMA dispatches)
constexpr int TN = 256;         // N per CTA
constexpr int TK = 32;          // K elems per stage (128B per row)
constexpr int NS = 3;           // pipeline stages
constexpr int STAGE_BYTES = (TMM + TN) * 128;           // 65536
constexpr int SMEM_TOTAL = 1024 + NS * STAGE_BYTES;     // 197632
constexpr int NTHREADS = 288;   // 256 producer/epilogue + 32 MMA issuer

// idesc: c=F32(1), a=TF32(2), b=TF32(2), K-major both, N=256, M=128 (per dispatch)
constexpr uint32_t IDESC =
    (1u << 4) | (2u << 7) | (2u << 10) | ((TN / 8) << 17) | ((128 / 16) << 24);

#define OFF_TMEM   0
#define OFF_FULL(s)  (8 + 8*(s))
#define OFF_EMPTY(s) (8 + 8*NS + 8*(s))
#define OFF_FIN      (8 + 16*NS)

// ---------------- scratch (device globals) ---------------------------------
__device__ float g_xr  [(long long)MTOT * Ed];
__device__ float g_qk  [(long long)2 * MTOT * Ed];   // q | k contiguous
__device__ float g_vt  [(long long)MTOT * Ed];       // V transposed [E,S] per batch
__device__ float g_at  [(long long)Bd * Sd * Sd];
__device__ float g_ao  [(long long)MTOT * Ed];
__device__ float g_tmp [(long long)MTOT * Ed];
__device__ float g_h1  [(long long)MTOT * Ed];
__device__ float g_ff  [(long long)MTOT * Fd];
__device__ float g_wt  [(long long)3 * Ed * Ed];     // Wq^T | Wk^T | Wv^T
__device__ float g_b2  [2 * Ed];
__device__ float g_wdt [(long long)Ed * Ed];
__device__ float g_wit [(long long)Fd * Ed];
__device__ float g_wot [(long long)Ed * Fd];

// ---------------- PTX helpers -------------------------------------------------
__device__ __forceinline__ uint32_t smem_u32(const void* p) {
    uint32_t a;
    asm("{ .reg .u64 t; cvta.to.shared.u64 t, %1; cvt.u32.u64 %0, t; }" : "=r"(a) : "l"(p));
    return a;
}
__device__ __forceinline__ uint32_t elect_one() {
    uint32_t p;
    asm volatile("{ .reg .pred p; elect.sync _|p, 0xFFFFFFFF; selp.b32 %0,1,0,p; }" : "=r"(p));
    return p;
}
__device__ __forceinline__ void mbar_init(uint32_t a, uint32_t c) {
    asm volatile("mbarrier.init.shared.b64 [%0], %1;" :: "r"(a), "r"(c) : "memory");
}
__device__ __forceinline__ void mbar_arrive(uint32_t a) {
    asm volatile("mbarrier.arrive.shared.b64 _, [%0];" :: "r"(a) : "memory");
}
__device__ __forceinline__ void mbar_wait(uint32_t a, uint32_t ph) {
    uint32_t done;
    asm volatile(
        "{\n\t.reg .pred p;\n\t"
        "mbarrier.try_wait.parity.acquire.cta.shared::cta.b64 p, [%1], %2;\n\t"
        "selp.b32 %0, 1, 0, p;\n\t}"
        : "=r"(done) : "r"(a), "r"(ph) : "memory");
    if (!done) {
        asm volatile(
            "{\n\t.reg .pred P1;\n\t"
            "WL%=:\n\t"
            "mbarrier.try_wait.parity.acquire.cta.shared::cta.b64 P1, [%0], %1, 0x989680;\n\t"
            "@P1 bra.uni WD%=;\n\t"
            "bra.uni WL%=;\n\t"
            "WD%=:\n\t}"
            :: "r"(a), "r"(ph) : "memory");
    }
}
__device__ __forceinline__ void cp16(uint32_t dst, const void* src) {
    asm volatile("cp.async.cg.shared.global [%0], [%1], 16;" :: "r"(dst), "l"(src) : "memory");
}
__device__ __forceinline__ uint64_t make_desc(uint32_t addr) {
    // SW128, version=1 (Blackwell), SBO=64, LBO=1
    return 0x4000404000010000ULL | ((uint64_t)(addr >> 4) & 0x3FFF);
}
__device__ __forceinline__ float rna_tf32(float x) {
    uint32_t u;
    asm("cvt.rna.tf32.f32 %0, %1;" : "=r"(u) : "f"(x));
    return __uint_as_float(u);
}

#if HAS_TC
__device__ __forceinline__ void mma_tf32(uint32_t d, uint64_t ad, uint64_t bd,
                                         uint32_t idesc, uint32_t en) {
    asm volatile(
        "{\n\t.reg .pred p;\n\t"
        "setp.ne.u32 p, %4, 0;\n\t"
        "tcgen05.mma.cta_group::1.kind::tf32 [%0], %1, %2, %3, {%5, %5, %5, %5}, p;\n\t}"
        :: "r"(d), "l"(ad), "l"(bd), "r"(idesc), "r"(en), "r"(0u)
        : "memory");
}
#define TC_ALLOC(sa, n)   asm volatile("tcgen05.alloc.cta_group::1.sync.aligned.shared::cta.b32 [%0], %1;" :: "r"(sa), "r"(n) : "memory")
#define TC_DEALLOC(t, n)  asm volatile("tcgen05.dealloc.cta_group::1.sync.aligned.b32 %0, %1;" :: "r"(t), "r"(n))
#define TC_RELINQ()       asm volatile("tcgen05.relinquish_alloc_permit.cta_group::1.sync.aligned;")
#define TC_COMMIT(mb)     asm volatile("tcgen05.commit.cta_group::1.mbarrier::arrive::one.shared::cluster.b64 [%0];" :: "r"(mb) : "memory")
#define TC_FENCE_AFTER()  asm volatile("tcgen05.fence::after_thread_sync;" ::: "memory")
#define TC_WAIT_LD()      asm volatile("tcgen05.wait::ld.sync.aligned;" ::: "memory")

#define LDTM_X32(r, ta) \
    asm volatile( \
        "tcgen05.ld.sync.aligned.32x32b.x32.b32 " \
        "{%0, %1, %2, %3, %4, %5, %6, %7, " \
        " %8, %9, %10, %11, %12, %13, %14, %15, " \
        " %16, %17, %18, %19, %20, %21, %22, %23, " \
        " %24, %25, %26, %27, %28, %29, %30, %31}, [%32];" \
        : "=r"((r)[0]),  "=r"((r)[1]),  "=r"((r)[2]),  "=r"((r)[3]), \
          "=r"((r)[4]),  "=r"((r)[5]),  "=r"((r)[6]),  "=r"((r)[7]), \
          "=r"((r)[8]),  "=r"((r)[9]),  "=r"((r)[10]), "=r"((r)[11]), \
          "=r"((r)[12]), "=r"((r)[13]), "=r"((r)[14]), "=r"((r)[15]), \
          "=r"((r)[16]), "=r"((r)[17]), "=r"((r)[18]), "=r"((r)[19]), \
          "=r"((r)[20]), "=r"((r)[21]), "=r"((r)[22]), "=r"((r)[23]), \
          "=r"((r)[24]), "=r"((r)[25]), "=r"((r)[26]), "=r"((r)[27]), \
          "=r"((r)[28]), "=r"((r)[29]), "=r"((r)[30]), "=r"((r)[31]) \
        : "r"(ta))
#endif // HAS_TC

// ---------------- tcgen05 TF32 GEMM (256x256 tile, cg1) ------------------------
// C = act(alpha * A @ Bt^T + bias + resid), A [M,K] K-major, Bt [N,K] K-major.
// 256 producer/epilogue threads (8 warps) + warp 8 = MMA issuer.
// Per stage: A panel 256 rows + B panel 256 rows (64KB). Two M=128 MMA dispatches
// per K-step accumulate into TMEM halves D0 (cols 0-255) and D1 (cols 256-511).
// BROW: bias indexed by output ROW (for computing V^T directly); else by column.
template<int ACT, bool ROUND, bool BROW>
__global__ void __launch_bounds__(NTHREADS, 1)
tc_gemm(const float* __restrict__ A, const float* __restrict__ Bt,
        const float* __restrict__ bias, const float* __restrict__ resid,
        float* __restrict__ C, int K, int N, float alpha,
        long long sA, long long sB, long long sC, long long sBias)
{
#if HAS_TC
    extern __shared__ char smem[];
    const uint32_t sb = smem_u32(smem);
    const int tid = threadIdx.x;
    const int wid = tid >> 5;

    A    += blockIdx.z * sA;
    Bt   += blockIdx.z * sB;
    C    += blockIdx.z * sC;
    if (bias) bias += blockIdx.z * sBias;
    const int bm = blockIdx.y * TMM;
    const int bn = blockIdx.x * TN;
    const int nk = K / TK;

    if (tid == 0) {
        for (int s = 0; s < NS; s++) {
            mbar_init(sb + OFF_FULL(s), 256);   // 256 producer threads
            mbar_init(sb + OFF_EMPTY(s), 1);
        }
        mbar_init(sb + OFF_FIN, 1);
    }
    if (wid == 8) {
        TC_ALLOC(sb + OFF_TMEM, 512);
        TC_RELINQ();
    }
    __syncthreads();
    uint32_t tmem;
    asm volatile("ld.shared.b32 %0, [%1];" : "=r"(tmem) : "r"(sb + OFF_TMEM));

    if (tid < 256) {
        // ---- producer: coalesced cp.async, 16 x 16B per thread per stage ----
        // a = tid>>3 (row phase 0..31), c = tid&7 (16B chunk). Rows a+32m, m=0..7
        // for each of the A (256-row) and B (256-row) panels.
        const int a = tid >> 3;
        const int c = tid & 7;
        const float* pA = A  + (long long)(bm + a) * K + c * 4;
        const float* pB = Bt + (long long)(bn + a) * K + c * 4;
        uint32_t o0 = (uint32_t)(a * 128 + c * 16);
        const uint32_t swA = o0 ^ ((o0 >> 3) & 0x70);   // row bits 0-2 = a&7, invariant in m
        const long long str32 = 32LL * K;

        int s = 0; uint32_t eph = 1;
        for (int kt = 0; kt < nk; kt++) {
            mbar_wait(sb + OFF_EMPTY(s), eph);
            const uint32_t st = sb + 1024 + s * STAGE_BYTES;
            #pragma unroll
            for (int m = 0; m < 8; m++)
                cp16(st + swA + m * 4096, pA + m * str32);
            #pragma unroll
            for (int m = 0; m < 8; m++)
                cp16(st + swA + 32768 + m * 4096, pB + m * str32);
            asm volatile("cp.async.commit_group;" ::: "memory");
            pA += TK; pB += TK;
            if (kt >= NS - 1) {
                asm volatile("cp.async.wait_group %0;" :: "n"(NS - 1) : "memory");
                asm volatile("fence.proxy.async.shared::cta;" ::: "memory");
                mbar_arrive(sb + OFF_FULL((kt - (NS - 1)) % NS));
            }
            if (++s == NS) { s = 0; eph ^= 1; }
        }
        asm volatile("cp.async.wait_group 0;" ::: "memory");
        asm volatile("fence.proxy.async.shared::cta;" ::: "memory");
        for (int j = nk - (NS - 1); j < nk; j++)
            mbar_arrive(sb + OFF_FULL(j % NS));

        // ---- epilogue: 8 warps cover both TMEM halves in parallel ----
        mbar_wait(sb + OFF_FIN, 0);
        TC_FENCE_AFTER();
        const int lane = tid & 31;
        const int h = wid >> 2;                 // TMEM half (M block)
        const long long row = bm + h * 128 + (wid & 3) * 32 + lane;
        float* crow = C + row * (long long)N + bn;
        const float* rrow = resid ? resid + row * (long long)N + bn : nullptr;
        float brow = 0.0f;
        if (BROW && bias) brow = bias[row];
        const uint32_t tmh = tmem + h * 256;

        #pragma unroll 1
        for (int cb = 0; cb < 8; cb++) {
            uint32_t r[32];
            LDTM_X32(r, tmh + cb * 32);
            TC_WAIT_LD();
            float v[32];
            #pragma unroll
            for (int j = 0; j < 32; j++) v[j] = __uint_as_float(r[j]) * alpha;
            if (bias) {
                if (BROW) {
                    #pragma unroll
                    for (int j = 0; j < 32; j++) v[j] += brow;
                } else {
                    #pragma unroll
                    for (int j0 = 0; j0 < 32; j0 += 4) {
                        float4 bb = *reinterpret_cast<const float4*>(bias + bn + cb * 32 + j0);
                        v[j0+0] += bb.x; v[j0+1] += bb.y; v[j0+2] += bb.z; v[j0+3] += bb.w;
                    }
                }
            }
            if (rrow) {
                #pragma unroll
                for (int j0 = 0; j0 < 32; j0 += 4) {
                    float4 rv = *reinterpret_cast<const float4*>(rrow + cb * 32 + j0);
                    v[j0+0] += rv.x; v[j0+1] += rv.y; v[j0+2] += rv.z; v[j0+3] += rv.w;
                }
            }
            if constexpr (ACT == 1) {
                #pragma unroll
                for (int j = 0; j < 32; j++)
                    v[j] = 0.5f * v[j] * (1.0f + erff(v[j] * 0.70710678118654752f));
            }
            if constexpr (ROUND) {
                #pragma unroll
                for (int j = 0; j < 32; j++) v[j] = rna_tf32(v[j]);
            }
            #pragma unroll
            for (int j0 = 0; j0 < 32; j0 += 4) {
                float4 o; o.x = v[j0]; o.y = v[j0+1]; o.z = v[j0+2]; o.w = v[j0+3];
                *reinterpret_cast<float4*>(crow + cb * 32 + j0) = o;
            }
        }
    } else {
        // ---- warp 8: MMA issuer (2 dispatches per K-step: M halves) ----
        uint32_t ep = elect_one();
        int s = 0; uint32_t ph = 0;
        for (int kt = 0; kt < nk; kt++) {
            mbar_wait(sb + OFF_FULL(s), ph);
            if (ep) {
                const uint32_t st = sb + 1024 + s * STAGE_BYTES;
                uint64_t ad0 = make_desc(st);
                uint64_t ad1 = make_desc(st + 16384);
                uint64_t bd  = make_desc(st + 32768);
                const uint32_t en0 = (uint32_t)(kt != 0);
                #pragma unroll
                for (int j = 0; j < 4; j++) {
                    const uint32_t en = en0 | (uint32_t)(j != 0);
                    mma_tf32(tmem,       ad0 + 2 * j, bd + 2 * j, IDESC, en);
                    mma_tf32(tmem + 256, ad1 + 2 * j, bd + 2 * j, IDESC, en);
                }
                if (kt == nk - 1) TC_COMMIT(sb + OFF_FIN);
                else              TC_COMMIT(sb + OFF_EMPTY(s));
            }
            if (++s == NS) { s = 0; ph ^= 1; }
        }
    }

    __syncthreads();
    if (wid == 8) TC_DEALLOC(tmem, 512);
#endif // HAS_TC
}

// ---------------- elementwise kernels ---------------------------------------
__device__ __forceinline__ float block_sum(float v, float* sh) {
    const int lane = threadIdx.x & 31, w = threadIdx.x >> 5;
    #pragma unroll
    for (int o = 16; o; o >>= 1) v += __shfl_xor_sync(0xffffffffu, v, o);
    __syncthreads();
    if (lane == 0) sh[w] = v;
    __syncthreads();
    float s = 0.f;
    #pragma unroll
    for (int i = 0; i < 8; i++) s += sh[i];
    return s;
}
__device__ __forceinline__ float block_max(float v, float* sh) {
    const int lane = threadIdx.x & 31, w = threadIdx.x >> 5;
    #pragma unroll
    for (int o = 16; o; o >>= 1) v = fmaxf(v, __shfl_xor_sync(0xffffffffu, v, o));
    __syncthreads();
    if (lane == 0) sh[w] = v;
    __syncthreads();
    float s = -INFINITY;
    #pragma unroll
    for (int i = 0; i < 8; i++) s = fmaxf(s, sh[i]);
    return s;
}

__global__ void __launch_bounds__(256) softmax_kernel(float* __restrict__ data)
{
    __shared__ float sh[8];
    const long long row = blockIdx.x;
    float4* p = reinterpret_cast<float4*>(data + row * 1024);
    float4 x = p[threadIdx.x];
    float m = fmaxf(fmaxf(x.x, x.y), fmaxf(x.z, x.w));
    m = block_max(m, sh);
    x.x = expf(x.x - m); x.y = expf(x.y - m);
    x.z = expf(x.z - m); x.w = expf(x.w - m);
    float s = x.x + x.y + x.z + x.w;
    s = block_sum(s, sh);
    const float inv = 1.0f / s;
    x.x = rna_tf32(x.x * inv); x.y = rna_tf32(x.y * inv);
    x.z = rna_tf32(x.z * inv); x.w = rna_tf32(x.w * inv);
    p[threadIdx.x] = x;
}

template<bool ROUND>
__global__ void __launch_bounds__(256)
ln_kernel(const float* __restrict__ in, const float* __restrict__ g,
          const float* __restrict__ b, float* __restrict__ out)
{
    __shared__ float sh[8];
    const long long row = blockIdx.x;
    const float4* p = reinterpret_cast<const float4*>(in + row * 1024);
    float4 x = p[threadIdx.x];
    float s = x.x + x.y + x.z + x.w;
    s = block_sum(s, sh);
    const float mu = s * (1.0f / 1024.0f);
    const float dx = x.x - mu, dy = x.y - mu, dz = x.z - mu, dw = x.w - mu;
    float ss = dx * dx + dy * dy + dz * dz + dw * dw;
    ss = block_sum(ss, sh);
    const float rstd = rsqrtf(ss * (1.0f / 1024.0f) + 1e-12f);
    const float4 gg = reinterpret_cast<const float4*>(g)[threadIdx.x];
    const float4 bb = reinterpret_cast<const float4*>(b)[threadIdx.x];
    float4 o;
    o.x = dx * rstd * gg.x + bb.x;
    o.y = dy * rstd * gg.y + bb.y;
    o.z = dz * rstd * gg.z + bb.z;
    o.w = dw * rstd * gg.w + bb.w;
    if (ROUND) { o.x = rna_tf32(o.x); o.y = rna_tf32(o.y); o.z = rna_tf32(o.z); o.w = rna_tf32(o.w); }
    reinterpret_cast<float4*>(out + row * 1024)[threadIdx.x] = o;
}

// Fast 64x64 transpose body shared by the generic and fused-4 kernels.
template<bool ROUND>
__device__ __forceinline__ void transpose_body(const float* __restrict__ in,
                                               float* __restrict__ out,
                                               int R, int C, int r0, int c0)
{
    __shared__ float t[64][65];
    const int fc = (threadIdx.x & 15) * 4;   // 0..60
    const int fr = threadIdx.x >> 4;         // 0..15

    #pragma unroll
    for (int i = 0; i < 4; i++) {
        const int r = fr + i * 16;
        float4 x = *reinterpret_cast<const float4*>(in + (long long)(r0 + r) * C + c0 + fc);
        t[fc + 0][r] = x.x; t[fc + 1][r] = x.y; t[fc + 2][r] = x.z; t[fc + 3][r] = x.w;
    }
    __syncthreads();
    #pragma unroll
    for (int i = 0; i < 4; i++) {
        const int oc = fr + i * 16;
        float4 y;
        y.x = t[oc][fc + 0]; y.y = t[oc][fc + 1];
        y.z = t[oc][fc + 2]; y.w = t[oc][fc + 3];
        if (ROUND) {
            y.x = rna_tf32(y.x); y.y = rna_tf32(y.y);
            y.z = rna_tf32(y.z); y.w = rna_tf32(y.w);
        }
        *reinterpret_cast<float4*>(out + (long long)(c0 + oc) * R + r0 + fc) = y;
    }
}

// Generic: in [R, C]; grid = (C/64, R/64, batch).
template<bool ROUND>
__global__ void __launch_bounds__(256)
transpose_fast(const float* __restrict__ in, float* __restrict__ out,
               int R, int C, long long sIn, long long sOut)
{
    transpose_body<ROUND>(in + blockIdx.z * sIn, out + blockIdx.z * sOut,
                          R, C, blockIdx.y * 64, blockIdx.x * 64);
}

// Fused transpose of four 1024x1024 weights (z selects which).
__global__ void __launch_bounds__(256)
transpose4(const float* __restrict__ w0, const float* __restrict__ w1,
           const float* __restrict__ w2, const float* __restrict__ w3,
           float* __restrict__ o0, float* __restrict__ o1,
           float* __restrict__ o2, float* __restrict__ o3)
{
    const float* in = blockIdx.z == 0 ? w0 : blockIdx.z == 1 ? w1 : blockIdx.z == 2 ? w2 : w3;
    float* out      = blockIdx.z == 0 ? o0 : blockIdx.z == 1 ? o1 : blockIdx.z == 2 ? o2 : o3;
    transpose_body<true>(in, out, 1024, 1024, blockIdx.y * 64, blockIdx.x * 64);
}

// Blocks 0..255: grid-stride RNA-round of x into xr.
// Blocks 256/257: copy bq/bk into the concatenated b2 buffer.
__global__ void __launch_bounds__(256)
round_bias_kernel(const float4* __restrict__ in, float4* __restrict__ out, long long n4,
                  const float4* __restrict__ bq, const float4* __restrict__ bk,
                  float4* __restrict__ b2)
{
    if (blockIdx.x >= 256) {
        const float4* src = (blockIdx.x == 256) ? bq : bk;
        b2[(blockIdx.x - 256) * 256 + threadIdx.x] = src[threadIdx.x];
        return;
    }
    for (long long i = blockIdx.x * 256LL + threadIdx.x; i < n4; i += 256LL * 256LL) {
        float4 v = in[i];
        v.x = rna_tf32(v.x); v.y = rna_tf32(v.y);
        v.z = rna_tf32(v.z); v.w = rna_tf32(v.w);
        out[i] = v;
    }
}

// ---------------- host launcher -----------------------------------------------
extern "C" void kernel_launch(void* const* d_in, const int* in_sizes, int n_in,
                              void* d_out, int out_size)
{
    const float* x  = (const float*)d_in[0];
    const float* Wq = (const float*)d_in[1];
    const float* bq = (const float*)d_in[2];
    const float* Wk = (const float*)d_in[3];
    const float* bk = (const float*)d_in[4];
    const float* Wv = (const float*)d_in[5];
    const float* bv = (const float*)d_in[6];
    const float* Wd = (const float*)d_in[7];
    const float* bd = (const float*)d_in[8];
    const float* g1 = (const float*)d_in[9];
    const float* b1 = (const float*)d_in[10];
    const float* Wi = (const float*)d_in[11];
    const float* bi = (const float*)d_in[12];
    const float* Wo = (const float*)d_in[13];
    const float* bo = (const float*)d_in[14];
    const float* g2 = (const float*)d_in[15];
    const float* b2 = (const float*)d_in[16];
    float* out = (float*)d_out;

    float *xr, *qk, *vt, *at, *ao, *tmp, *h1, *ff;
    float *wt, *b2qk, *wdt, *wit, *wot;
    cudaGetSymbolAddress((void**)&xr,   g_xr);
    cudaGetSymbolAddress((void**)&qk,   g_qk);
    cudaGetSymbolAddress((void**)&vt,   g_vt);
    cudaGetSymbolAddress((void**)&at,   g_at);
    cudaGetSymbolAddress((void**)&ao,   g_ao);
    cudaGetSymbolAddress((void**)&tmp,  g_tmp);
    cudaGetSymbolAddress((void**)&h1,   g_h1);
    cudaGetSymbolAddress((void**)&ff,   g_ff);
    cudaGetSymbolAddress((void**)&wt,   g_wt);
    cudaGetSymbolAddress((void**)&b2qk, g_b2);
    cudaGetSymbolAddress((void**)&wdt,  g_wdt);
    cudaGetSymbolAddress((void**)&wit,  g_wit);
    cudaGetSymbolAddress((void**)&wot,  g_wot);

    cudaFuncSetAttribute(tc_gemm<0, true,  false>, cudaFuncAttributeMaxDynamicSharedMemorySize, SMEM_TOTAL);
    cudaFuncSetAttribute(tc_gemm<0, true,  true >, cudaFuncAttributeMaxDynamicSharedMemorySize, SMEM_TOTAL);
    cudaFuncSetAttribute(tc_gemm<0, false, false>, cudaFuncAttributeMaxDynamicSharedMemorySize, SMEM_TOTAL);
    cudaFuncSetAttribute(tc_gemm<1, true,  false>, cudaFuncAttributeMaxDynamicSharedMemorySize, SMEM_TOTAL);

    const long long ME = (long long)MTOT * Ed;
    const long long SE = (long long)Sd * Ed;
    const long long SS = (long long)Sd * Sd;
    const long long EE = (long long)Ed * Ed;
    float* q = qk;
    float* k = qk + ME;
    const dim3 tb(256);
    const dim3 gt(NTHREADS);

    // 0: round x -> xr and build [bq|bk]
    round_bias_kernel<<<258, tb>>>((const float4*)x, (float4*)xr, ME / 4,
                                   (const float4*)bq, (const float4*)bk, (float4*)b2qk);
    // 1: all four 1024x1024 weight transposes in one launch
    transpose4<<<dim3(16, 16, 4), tb>>>(Wq, Wk, Wv, Wd, wt, wt + EE, wt + 2 * EE, wdt);
    // 2: Wi transpose ([Ed, Fd] -> grid (Fd/64, Ed/64))
    transpose_fast<true><<<dim3(Fd/64, Ed/64, 1), tb>>>(Wi, wit, Ed, Fd, 0, 0);
    // 3: fused Q,K projections  <-- profiled launch (harness offset 2 => ncu -s 5)
    tc_gemm<0, true, false><<<dim3(Ed/TN, MTOT/TMM, 2), gt, SMEM_TOTAL>>>(
        xr, wt, b2qk, nullptr, qk, Ed, Ed, 1.0f, 0, EE, ME, Ed);
    // 4: Wo transpose ([Fd, Ed] -> grid (Ed/64, Fd/64))
    transpose_fast<true><<<dim3(Ed/64, Fd/64, 1), tb>>>(Wo, wot, Fd, Ed, 0, 0);
    // 5: vt = Wv^T @ x^T + bv (per batch) -> [E, S], row-bias epilogue
    tc_gemm<0, true, true><<<dim3(Sd/TN, Ed/TMM, Bd), gt, SMEM_TOTAL>>>(
        wt + 2 * EE, xr, bv, nullptr, vt, Ed, Sd, 1.0f, 0, SE, SE, 0);
    // 6: scores = q @ k^T / 32
    tc_gemm<0, false, false><<<dim3(Sd/TN, Sd/TMM, Bd), gt, SMEM_TOTAL>>>(
        q, k, nullptr, nullptr, at, Ed, Sd, 0.03125f, SE, SE, SS, 0);
    // 7: softmax (RNA-rounded)
    softmax_kernel<<<Bd * Sd, tb>>>(at);
    // 8: attn_out = attn_w @ v (Bt = vt, [E,S] K-major)
    tc_gemm<0, true, false><<<dim3(Ed/TN, Sd/TMM, Bd), gt, SMEM_TOTAL>>>(
        at, vt, nullptr, nullptr, ao, Sd, Ed, 1.0f, SS, SE, SE, 0);
    // 9-10: Wd GEMM (+bias +resid x) then LN1
    tc_gemm<0, false, false><<<dim3(Ed/TN, MTOT/TMM, 1), gt, SMEM_TOTAL>>>(
        ao, wdt, bd, x, tmp, Ed, Ed, 1.0f, 0, 0, 0, 0);
    ln_kernel<true><<<MTOT, tb>>>(tmp, g1, b1, h1);
    // 11: ff = gelu(h1 @ Wi + bi)
    tc_gemm<1, true, false><<<dim3(Fd/TN, MTOT/TMM, 1), gt, SMEM_TOTAL>>>(
        h1, wit, bi, nullptr, ff, Ed, Fd, 1.0f, 0, 0, 0, 0);
    // 12-13: out = LN(ff @ Wo + bo + h1)
    tc_gemm<0, false, false><<<dim3(Ed/TN, MTOT/TMM, 1), gt, SMEM_TOTAL>>>(
        ff, wot, bo, h1, tmp, Fd, Ed, 1.0f, 0, 0, 0, 0);
    ln_kernel<false><<<MTOT, tb>>>(tmp, g2, b2, out);
}

// round 9
// speedup vs baseline: 1.9176x; 1.1987x over previous
#include <cuda_runtime.h>
#include <math.h>
#include <stdint.h>

// tcgen05 is an architecture-specific feature: only emit it in the sm_103a/sm_100a
// compilation passes. Non-'a' passes get an empty stub body.
#if defined(__CUDA_ARCH_FEAT_SM103_ALL) || defined(__CUDA_ARCH_FEAT_SM100_ALL) || defined(__CUDA_ARCH_FEAT_SM101_ALL) || defined(__CUDA_ARCH_FEAT_SM110_ALL)
#define HAS_TC 1
#else
#define HAS_TC 0
#endif

// Problem dims
constexpr int Bd = 8;
constexpr int Sd = 1024;
constexpr int Ed = 1024;
constexpr int Fd = 4096;
constexpr int MTOT = Bd * Sd;   // 8192

// tcgen05 GEMM tile config: 256x256 tile = 2 x (128x256) MMA into TMEM halves
constexpr int TMM = 256;        // M per tile (two 128-row MMA dispatches)
constexpr int TN = 256;         // N per tile
constexpr int TK = 32;          // K elems per stage (128B per row)
constexpr int NS = 3;           // pipeline stages
constexpr int STAGE_BYTES = (TMM + TN) * 128;           // 65536
constexpr int SMEM_TOTAL = 1024 + NS * STAGE_BYTES;     // 197632
constexpr int NTHREADS = 288;   // 4 producer warps + 4 epilogue warps + 1 MMA warp
constexpr int GRID = 128;       // persistent CTAs (all tile counts are multiples of 128)

// idesc: c=F32(1), a=TF32(2), b=TF32(2), K-major both, N=256, M=128 (per dispatch)
constexpr uint32_t IDESC =
    (1u << 4) | (2u << 7) | (2u << 10) | ((TN / 8) << 17) | ((128 / 16) << 24);

#define OFF_TMEM   0
#define OFF_FULL(s)  (8 + 8*(s))
#define OFF_EMPTY(s) (8 + 8*NS + 8*(s))
#define OFF_FIN      (8 + 16*NS)
#define OFF_TFREE    (8 + 16*NS + 8)

// ---------------- scratch (device globals) ---------------------------------
__device__ float g_xr  [(long long)MTOT * Ed];
__device__ float g_qk  [(long long)2 * MTOT * Ed];   // q | k contiguous
__device__ float g_vt  [(long long)MTOT * Ed];       // V transposed [E,S] per batch
__device__ float g_at  [(long long)Bd * Sd * Sd];
__device__ float g_ao  [(long long)MTOT * Ed];
__device__ float g_tmp [(long long)MTOT * Ed];
__device__ float g_h1  [(long long)MTOT * Ed];
__device__ float g_ff  [(long long)MTOT * Fd];
__device__ float g_wt  [(long long)3 * Ed * Ed];     // Wq^T | Wk^T | Wv^T
__device__ float g_b2  [2 * Ed];
__device__ float g_wdt [(long long)Ed * Ed];
__device__ float g_wit [(long long)Fd * Ed];
__device__ float g_wot [(long long)Ed * Fd];

// ---------------- PTX helpers -------------------------------------------------
__device__ __forceinline__ uint32_t smem_u32(const void* p) {
    uint32_t a;
    asm("{ .reg .u64 t; cvta.to.shared.u64 t, %1; cvt.u32.u64 %0, t; }" : "=r"(a) : "l"(p));
    return a;
}
__device__ __forceinline__ uint32_t elect_one() {
    uint32_t p;
    asm volatile("{ .reg .pred p; elect.sync _|p, 0xFFFFFFFF; selp.b32 %0,1,0,p; }" : "=r"(p));
    return p;
}
__device__ __forceinline__ void mbar_init(uint32_t a, uint32_t c) {
    asm volatile("mbarrier.init.shared.b64 [%0], %1;" :: "r"(a), "r"(c) : "memory");
}
__device__ __forceinline__ void mbar_arrive(uint32_t a) {
    asm volatile("mbarrier.arrive.shared.b64 _, [%0];" :: "r"(a) : "memory");
}
__device__ __forceinline__ void mbar_wait(uint32_t a, uint32_t ph) {
    uint32_t done;
    asm volatile(
        "{\n\t.reg .pred p;\n\t"
        "mbarrier.try_wait.parity.acquire.cta.shared::cta.b64 p, [%1], %2;\n\t"
        "selp.b32 %0, 1, 0, p;\n\t}"
        : "=r"(done) : "r"(a), "r"(ph) : "memory");
    if (!done) {
        asm volatile(
            "{\n\t.reg .pred P1;\n\t"
            "WL%=:\n\t"
            "mbarrier.try_wait.parity.acquire.cta.shared::cta.b64 P1, [%0], %1, 0x989680;\n\t"
            "@P1 bra.uni WD%=;\n\t"
            "bra.uni WL%=;\n\t"
            "WD%=:\n\t}"
            :: "r"(a), "r"(ph) : "memory");
    }
}
__device__ __forceinline__ void cp16(uint32_t dst, const void* src) {
    asm volatile("cp.async.cg.shared.global [%0], [%1], 16;" :: "r"(dst), "l"(src) : "memory");
}
// Async arrive: fires on the mbarrier once all prior cp.async of this thread complete.
__device__ __forceinline__ void cpasync_arrive(uint32_t a) {
    asm volatile("cp.async.mbarrier.arrive.noinc.shared::cta.b64 [%0];" :: "r"(a) : "memory");
}
__device__ __forceinline__ uint64_t make_desc(uint32_t addr) {
    // SW128, version=1 (Blackwell), SBO=64, LBO=1
    return 0x4000404000010000ULL | ((uint64_t)(addr >> 4) & 0x3FFF);
}
__device__ __forceinline__ float rna_tf32(float x) {
    uint32_t u;
    asm("cvt.rna.tf32.f32 %0, %1;" : "=r"(u) : "f"(x));
    return __uint_as_float(u);
}

#if HAS_TC
__device__ __forceinline__ void mma_tf32(uint32_t d, uint64_t ad, uint64_t bd,
                                         uint32_t idesc, uint32_t en) {
    asm volatile(
        "{\n\t.reg .pred p;\n\t"
        "setp.ne.u32 p, %4, 0;\n\t"
        "tcgen05.mma.cta_group::1.kind::tf32 [%0], %1, %2, %3, {%5, %5, %5, %5}, p;\n\t}"
        :: "r"(d), "l"(ad), "l"(bd), "r"(idesc), "r"(en), "r"(0u)
        : "memory");
}
#define TC_ALLOC(sa, n)   asm volatile("tcgen05.alloc.cta_group::1.sync.aligned.shared::cta.b32 [%0], %1;" :: "r"(sa), "r"(n) : "memory")
#define TC_DEALLOC(t, n)  asm volatile("tcgen05.dealloc.cta_group::1.sync.aligned.b32 %0, %1;" :: "r"(t), "r"(n))
#define TC_RELINQ()       asm volatile("tcgen05.relinquish_alloc_permit.cta_group::1.sync.aligned;")
#define TC_COMMIT(mb)     asm volatile("tcgen05.commit.cta_group::1.mbarrier::arrive::one.shared::cluster.b64 [%0];" :: "r"(mb) : "memory")
#define TC_FENCE_AFTER()  asm volatile("tcgen05.fence::after_thread_sync;" ::: "memory")
#define TC_FENCE_BEFORE() asm volatile("tcgen05.fence::before_thread_sync;" ::: "memory")
#define TC_WAIT_LD()      asm volatile("tcgen05.wait::ld.sync.aligned;" ::: "memory")

#define LDTM_X32(r, ta) \
    asm volatile( \
        "tcgen05.ld.sync.aligned.32x32b.x32.b32 " \
        "{%0, %1, %2, %3, %4, %5, %6, %7, " \
        " %8, %9, %10, %11, %12, %13, %14, %15, " \
        " %16, %17, %18, %19, %20, %21, %22, %23, " \
        " %24, %25, %26, %27, %28, %29, %30, %31}, [%32];" \
        : "=r"((r)[0]),  "=r"((r)[1]),  "=r"((r)[2]),  "=r"((r)[3]), \
          "=r"((r)[4]),  "=r"((r)[5]),  "=r"((r)[6]),  "=r"((r)[7]), \
          "=r"((r)[8]),  "=r"((r)[9]),  "=r"((r)[10]), "=r"((r)[11]), \
          "=r"((r)[12]), "=r"((r)[13]), "=r"((r)[14]), "=r"((r)[15]), \
          "=r"((r)[16]), "=r"((r)[17]), "=r"((r)[18]), "=r"((r)[19]), \
          "=r"((r)[20]), "=r"((r)[21]), "=r"((r)[22]), "=r"((r)[23]), \
          "=r"((r)[24]), "=r"((r)[25]), "=r"((r)[26]), "=r"((r)[27]), \
          "=r"((r)[28]), "=r"((r)[29]), "=r"((r)[30]), "=r"((r)[31]) \
        : "r"(ta))
#endif // HAS_TC

// ---------------- persistent warp-specialized tcgen05 TF32 GEMM ----------------
// C = act(alpha * A @ Bt^T + bias + resid), A [M,K] K-major, Bt [N,K] K-major.
// GRID persistent CTAs, each loops tiles t = blockIdx.x + i*GRID (T tiles total;
// tile decode: tz = t/gxy, ty = (t%gxy)/gx, tx = t%gx).
// Warps 0-3: cp.async producers with async mbarrier arrives (no wait_group).
// Warps 4-7: TMEM-drain epilogue (each warp reads its own subpartition).
// Warp 8:    MMA issuer; per stage 2 M-half dispatches into TMEM cols [0,256)/[256,512).
// Handoff: MMA commits FIN per tile -> epilogue reads TMEM -> arrives TFREE ->
// MMA starts next tile. Producers prefill next tile's stages during the epilogue.
template<int ACT, bool ROUND, bool BROW>
__global__ void __launch_bounds__(NTHREADS, 1)
tc_gemm(const float* __restrict__ A, const float* __restrict__ Bt,
        const float* __restrict__ bias, const float* __restrict__ resid,
        float* __restrict__ C, int K, int N, float alpha,
        long long sA, long long sB, long long sC, long long sBias,
        int T, int gx, int gxy)
{
#if HAS_TC
    extern __shared__ char smem[];
    const uint32_t sb = smem_u32(smem);
    const int tid = threadIdx.x;
    const int wid = tid >> 5;
    const int nk = K / TK;

    if (tid == 0) {
        for (int s = 0; s < NS; s++) {
            mbar_init(sb + OFF_FULL(s), 128);   // 128 producer threads
            mbar_init(sb + OFF_EMPTY(s), 1);    // tcgen05.commit arrive-one
        }
        mbar_init(sb + OFF_FIN, 1);             // tcgen05.commit arrive-one
        mbar_init(sb + OFF_TFREE, 128);         // 128 epilogue threads
    }
    if (wid == 8) {
        TC_ALLOC(sb + OFF_TMEM, 512);
        TC_RELINQ();
    }
    __syncthreads();
    uint32_t tmem;
    asm volatile("ld.shared.b32 %0, [%1];" : "=r"(tmem) : "r"(sb + OFF_TMEM));

    if (tid < 128) {
        // ---- producers: 32 x cp.async(16B) per thread per stage, async arrive ----
        const int a = tid >> 3;          // row phase 0..15
        const int c = tid & 7;           // 16B chunk within 128B row
        uint32_t o0 = (uint32_t)(a * 128 + c * 16);
        const uint32_t swz = o0 ^ ((o0 >> 3) & 0x70);   // invariant under row += 16
        const long long str16 = 16LL * K;

        int s = 0; uint32_t eph = 1;
        for (int t = blockIdx.x; t < T; t += GRID) {
            const int tz = t / gxy;
            const int rem = t - tz * gxy;
            const int ty = rem / gx;
            const int tx = rem - ty * gx;
            const float* pA = A  + (long long)tz * sA + (long long)(ty * TMM + a) * K + c * 4;
            const float* pB = Bt + (long long)tz * sB + (long long)(tx * TN  + a) * K + c * 4;
            for (int kt = 0; kt < nk; kt++) {
                mbar_wait(sb + OFF_EMPTY(s), eph);
                const uint32_t st = sb + 1024 + s * STAGE_BYTES;
                #pragma unroll
                for (int m = 0; m < 16; m++)
                    cp16(st + swz + m * 2048, pA + m * str16);
                #pragma unroll
                for (int m = 0; m < 16; m++)
                    cp16(st + swz + 32768 + m * 2048, pB + m * str16);
                cpasync_arrive(sb + OFF_FULL(s));
                pA += TK; pB += TK;
                if (++s == NS) { s = 0; eph ^= 1; }
            }
        }
    } else if (tid < 256) {
        // ---- epilogue warps: wid 4..7 -> subpartitions 0..3 ----
        const int lane = tid & 31;
        const int sp = wid & 3;
        int n = 0;
        for (int t = blockIdx.x; t < T; t += GRID, n++) {
            mbar_wait(sb + OFF_FIN, n & 1);
            TC_FENCE_AFTER();
            const int tz = t / gxy;
            const int rem = t - tz * gxy;
            const int ty = rem / gx;
            const int tx = rem - ty * gx;
            const int bm = ty * TMM, bn = tx * TN;
            const float* biasz = bias ? bias + (long long)tz * sBias : nullptr;

            #pragma unroll 1
            for (int h = 0; h < 2; h++) {
                const long long row = bm + h * 128 + sp * 32 + lane;
                float* crow = C + (long long)tz * sC + row * (long long)N + bn;
                const float* rrow = resid ? resid + (long long)tz * sC + row * (long long)N + bn
                                          : nullptr;
                float brow = 0.0f;
                if (BROW && biasz) brow = biasz[row];
                const uint32_t tmh = tmem + h * 256;

                #pragma unroll 1
                for (int cb = 0; cb < 8; cb++) {
                    uint32_t r[32];
                    LDTM_X32(r, tmh + cb * 32);
                    TC_WAIT_LD();
                    float v[32];
                    #pragma unroll
                    for (int j = 0; j < 32; j++) v[j] = __uint_as_float(r[j]) * alpha;
                    if (biasz) {
                        if (BROW) {
                            #pragma unroll
                            for (int j = 0; j < 32; j++) v[j] += brow;
                        } else {
                            #pragma unroll
                            for (int j0 = 0; j0 < 32; j0 += 4) {
                                float4 bb = *reinterpret_cast<const float4*>(biasz + bn + cb * 32 + j0);
                                v[j0+0] += bb.x; v[j0+1] += bb.y; v[j0+2] += bb.z; v[j0+3] += bb.w;
                            }
                        }
                    }
                    if (rrow) {
                        #pragma unroll
                        for (int j0 = 0; j0 < 32; j0 += 4) {
                            float4 rv = *reinterpret_cast<const float4*>(rrow + cb * 32 + j0);
                            v[j0+0] += rv.x; v[j0+1] += rv.y; v[j0+2] += rv.z; v[j0+3] += rv.w;
                        }
                    }
                    if constexpr (ACT == 1) {
                        #pragma unroll
                        for (int j = 0; j < 32; j++)
                            v[j] = 0.5f * v[j] * (1.0f + erff(v[j] * 0.70710678118654752f));
                    }
                    if constexpr (ROUND) {
                        #pragma unroll
                        for (int j = 0; j < 32; j++) v[j] = rna_tf32(v[j]);
                    }
                    #pragma unroll
                    for (int j0 = 0; j0 < 32; j0 += 4) {
                        float4 o; o.x = v[j0]; o.y = v[j0+1]; o.z = v[j0+2]; o.w = v[j0+3];
                        *reinterpret_cast<float4*>(crow + cb * 32 + j0) = o;
                    }
                }
            }
            // All TMEM reads for this tile are complete (WAIT_LD per block).
            TC_FENCE_BEFORE();
            mbar_arrive(sb + OFF_TFREE);
        }
    } else {
        // ---- warp 8: MMA issuer ----
        uint32_t ep = elect_one();
        int s = 0; uint32_t ph = 0; int n = 0;
        for (int t = blockIdx.x; t < T; t += GRID, n++) {
            mbar_wait(sb + OFF_TFREE, (n + 1) & 1);   // first wait passes (fresh barrier)
            TC_FENCE_AFTER();
            for (int kt = 0; kt < nk; kt++) {
                mbar_wait(sb + OFF_FULL(s), ph);
                if (ep) {
                    const uint32_t st = sb + 1024 + s * STAGE_BYTES;
                    uint64_t ad0 = make_desc(st);
                    uint64_t ad1 = make_desc(st + 16384);
                    uint64_t bd  = make_desc(st + 32768);
                    const uint32_t en0 = (uint32_t)(kt != 0);
                    #pragma unroll
                    for (int j = 0; j < 4; j++) {
                        const uint32_t en = en0 | (uint32_t)(j != 0);
                        mma_tf32(tmem,       ad0 + 2 * j, bd + 2 * j, IDESC, en);
                        mma_tf32(tmem + 256, ad1 + 2 * j, bd + 2 * j, IDESC, en);
                    }
                    TC_COMMIT(sb + OFF_EMPTY(s));
                    if (kt == nk - 1) TC_COMMIT(sb + OFF_FIN);
                }
                if (++s == NS) { s = 0; ph ^= 1; }
            }
        }
    }

    __syncthreads();
    if (wid == 8) TC_DEALLOC(tmem, 512);
#endif // HAS_TC
}

// ---------------- elementwise kernels ---------------------------------------
__device__ __forceinline__ float block_sum(float v, float* sh) {
    const int lane = threadIdx.x & 31, w = threadIdx.x >> 5;
    #pragma unroll
    for (int o = 16; o; o >>= 1) v += __shfl_xor_sync(0xffffffffu, v, o);
    __syncthreads();
    if (lane == 0) sh[w] = v;
    __syncthreads();
    float s = 0.f;
    #pragma unroll
    for (int i = 0; i < 8; i++) s += sh[i];
    return s;
}
__device__ __forceinline__ float block_max(float v, float* sh) {
    const int lane = threadIdx.x & 31, w = threadIdx.x >> 5;
    #pragma unroll
    for (int o = 16; o; o >>= 1) v = fmaxf(v, __shfl_xor_sync(0xffffffffu, v, o));
    __syncthreads();
    if (lane == 0) sh[w] = v;
    __syncthreads();
    float s = -INFINITY;
    #pragma unroll
    for (int i = 0; i < 8; i++) s = fmaxf(s, sh[i]);
    return s;
}

__global__ void __launch_bounds__(256) softmax_kernel(float* __restrict__ data)
{
    __shared__ float sh[8];
    const long long row = blockIdx.x;
    float4* p = reinterpret_cast<float4*>(data + row * 1024);
    float4 x = p[threadIdx.x];
    float m = fmaxf(fmaxf(x.x, x.y), fmaxf(x.z, x.w));
    m = block_max(m, sh);
    x.x = expf(x.x - m); x.y = expf(x.y - m);
    x.z = expf(x.z - m); x.w = expf(x.w - m);
    float s = x.x + x.y + x.z + x.w;
    s = block_sum(s, sh);
    const float inv = 1.0f / s;
    x.x = rna_tf32(x.x * inv); x.y = rna_tf32(x.y * inv);
    x.z = rna_tf32(x.z * inv); x.w = rna_tf32(x.w * inv);
    p[threadIdx.x] = x;
}

template<bool ROUND>
__global__ void __launch_bounds__(256)
ln_kernel(const float* __restrict__ in, const float* __restrict__ g,
          const float* __restrict__ b, float* __restrict__ out)
{
    __shared__ float sh[8];
    const long long row = blockIdx.x;
    const float4* p = reinterpret_cast<const float4*>(in + row * 1024);
    float4 x = p[threadIdx.x];
    float s = x.x + x.y + x.z + x.w;
    s = block_sum(s, sh);
    const float mu = s * (1.0f / 1024.0f);
    const float dx = x.x - mu, dy = x.y - mu, dz = x.z - mu, dw = x.w - mu;
    float ss = dx * dx + dy * dy + dz * dz + dw * dw;
    ss = block_sum(ss, sh);
    const float rstd = rsqrtf(ss * (1.0f / 1024.0f) + 1e-12f);
    const float4 gg = reinterpret_cast<const float4*>(g)[threadIdx.x];
    const float4 bb = reinterpret_cast<const float4*>(b)[threadIdx.x];
    float4 o;
    o.x = dx * rstd * gg.x + bb.x;
    o.y = dy * rstd * gg.y + bb.y;
    o.z = dz * rstd * gg.z + bb.z;
    o.w = dw * rstd * gg.w + bb.w;
    if (ROUND) { o.x = rna_tf32(o.x); o.y = rna_tf32(o.y); o.z = rna_tf32(o.z); o.w = rna_tf32(o.w); }
    reinterpret_cast<float4*>(out + row * 1024)[threadIdx.x] = o;
}

// Fast 64x64 transpose body shared by the generic and fused-4 kernels.
template<bool ROUND>
__device__ __forceinline__ void transpose_body(const float* __restrict__ in,
                                               float* __restrict__ out,
                                               int R, int C, int r0, int c0)
{
    __shared__ float t[64][65];
    const int fc = (threadIdx.x & 15) * 4;   // 0..60
    const int fr = threadIdx.x >> 4;         // 0..15

    #pragma unroll
    for (int i = 0; i < 4; i++) {
        const int r = fr + i * 16;
        float4 x = *reinterpret_cast<const float4*>(in + (long long)(r0 + r) * C + c0 + fc);
        t[fc + 0][r] = x.x; t[fc + 1][r] = x.y; t[fc + 2][r] = x.z; t[fc + 3][r] = x.w;
    }
    __syncthreads();
    #pragma unroll
    for (int i = 0; i < 4; i++) {
        const int oc = fr + i * 16;
        float4 y;
        y.x = t[oc][fc + 0]; y.y = t[oc][fc + 1];
        y.z = t[oc][fc + 2]; y.w = t[oc][fc + 3];
        if (ROUND) {
            y.x = rna_tf32(y.x); y.y = rna_tf32(y.y);
            y.z = rna_tf32(y.z); y.w = rna_tf32(y.w);
        }
        *reinterpret_cast<float4*>(out + (long long)(c0 + oc) * R + r0 + fc) = y;
    }
}

// Generic: in [R, C]; grid = (C/64, R/64, batch).
template<bool ROUND>
__global__ void __launch_bounds__(256)
transpose_fast(const float* __restrict__ in, float* __restrict__ out,
               int R, int C, long long sIn, long long sOut)
{
    transpose_body<ROUND>(in + blockIdx.z * sIn, out + blockIdx.z * sOut,
                          R, C, blockIdx.y * 64, blockIdx.x * 64);
}

// Fused transpose of four 1024x1024 weights (z selects which).
__global__ void __launch_bounds__(256)
transpose4(const float* __restrict__ w0, const float* __restrict__ w1,
           const float* __restrict__ w2, const float* __restrict__ w3,
           float* __restrict__ o0, float* __restrict__ o1,
           float* __restrict__ o2, float* __restrict__ o3)
{
    const float* in = blockIdx.z == 0 ? w0 : blockIdx.z == 1 ? w1 : blockIdx.z == 2 ? w2 : w3;
    float* out      = blockIdx.z == 0 ? o0 : blockIdx.z == 1 ? o1 : blockIdx.z == 2 ? o2 : o3;
    transpose_body<true>(in, out, 1024, 1024, blockIdx.y * 64, blockIdx.x * 64);
}

// Blocks 0..255: grid-stride RNA-round of x into xr.
// Blocks 256/257: copy bq/bk into the concatenated b2 buffer.
__global__ void __launch_bounds__(256)
round_bias_kernel(const float4* __restrict__ in, float4* __restrict__ out, long long n4,
                  const float4* __restrict__ bq, const float4* __restrict__ bk,
                  float4* __restrict__ b2)
{
    if (blockIdx.x >= 256) {
        const float4* src = (blockIdx.x == 256) ? bq : bk;
        b2[(blockIdx.x - 256) * 256 + threadIdx.x] = src[threadIdx.x];
        return;
    }
    for (long long i = blockIdx.x * 256LL + threadIdx.x; i < n4; i += 256LL * 256LL) {
        float4 v = in[i];
        v.x = rna_tf32(v.x); v.y = rna_tf32(v.y);
        v.z = rna_tf32(v.z); v.w = rna_tf32(v.w);
        out[i] = v;
    }
}

// ---------------- host launcher -----------------------------------------------
extern "C" void kernel_launch(void* const* d_in, const int* in_sizes, int n_in,
                              void* d_out, int out_size)
{
    const float* x  = (const float*)d_in[0];
    const float* Wq = (const float*)d_in[1];
    const float* bq = (const float*)d_in[2];
    const float* Wk = (const float*)d_in[3];
    const float* bk = (const float*)d_in[4];
    const float* Wv = (const float*)d_in[5];
    const float* bv = (const float*)d_in[6];
    const float* Wd = (const float*)d_in[7];
    const float* bd = (const float*)d_in[8];
    const float* g1 = (const float*)d_in[9];
    const float* b1 = (const float*)d_in[10];
    const float* Wi = (const float*)d_in[11];
    const float* bi = (const float*)d_in[12];
    const float* Wo = (const float*)d_in[13];
    const float* bo = (const float*)d_in[14];
    const float* g2 = (const float*)d_in[15];
    const float* b2 = (const float*)d_in[16];
    float* out = (float*)d_out;

    float *xr, *qk, *vt, *at, *ao, *tmp, *h1, *ff;
    float *wt, *b2qk, *wdt, *wit, *wot;
    cudaGetSymbolAddress((void**)&xr,   g_xr);
    cudaGetSymbolAddress((void**)&qk,   g_qk);
    cudaGetSymbolAddress((void**)&vt,   g_vt);
    cudaGetSymbolAddress((void**)&at,   g_at);
    cudaGetSymbolAddress((void**)&ao,   g_ao);
    cudaGetSymbolAddress((void**)&tmp,  g_tmp);
    cudaGetSymbolAddress((void**)&h1,   g_h1);
    cudaGetSymbolAddress((void**)&ff,   g_ff);
    cudaGetSymbolAddress((void**)&wt,   g_wt);
    cudaGetSymbolAddress((void**)&b2qk, g_b2);
    cudaGetSymbolAddress((void**)&wdt,  g_wdt);
    cudaGetSymbolAddress((void**)&wit,  g_wit);
    cudaGetSymbolAddress((void**)&wot,  g_wot);

    cudaFuncSetAttribute(tc_gemm<0, true,  false>, cudaFuncAttributeMaxDynamicSharedMemorySize, SMEM_TOTAL);
    cudaFuncSetAttribute(tc_gemm<0, true,  true >, cudaFuncAttributeMaxDynamicSharedMemorySize, SMEM_TOTAL);
    cudaFuncSetAttribute(tc_gemm<0, false, false>, cudaFuncAttributeMaxDynamicSharedMemorySize, SMEM_TOTAL);
    cudaFuncSetAttribute(tc_gemm<1, true,  false>, cudaFuncAttributeMaxDynamicSharedMemorySize, SMEM_TOTAL);

    const long long ME = (long long)MTOT * Ed;
    const long long SE = (long long)Sd * Ed;
    const long long SS = (long long)Sd * Sd;
    const long long EE = (long long)Ed * Ed;
    float* q = qk;
    float* k = qk + ME;
    const dim3 tb(256);
    const dim3 gt(NTHREADS);
    const dim3 gg(GRID);

    // 0: round x -> xr and build [bq|bk]
    round_bias_kernel<<<258, tb>>>((const float4*)x, (float4*)xr, ME / 4,
                                   (const float4*)bq, (const float4*)bk, (float4*)b2qk);
    // 1: all four 1024x1024 weight transposes in one launch
    transpose4<<<dim3(16, 16, 4), tb>>>(Wq, Wk, Wv, Wd, wt, wt + EE, wt + 2 * EE, wdt);
    // 2: Wi transpose ([Ed, Fd] -> grid (Fd/64, Ed/64))
    transpose_fast<true><<<dim3(Fd/64, Ed/64, 1), tb>>>(Wi, wit, Ed, Fd, 0, 0);
    // 3: fused Q,K projections  <-- profiled launch (harness offset 2 => ncu -s 5)
    //    tiles: gx=Ed/TN=4, gy=MTOT/TMM=32, gz=2 -> T=256, gxy=128
    tc_gemm<0, true, false><<<gg, gt, SMEM_TOTAL>>>(
        xr, wt, b2qk, nullptr, qk, Ed, Ed, 1.0f, 0, EE, ME, Ed, 256, 4, 128);
    // 4: Wo transpose ([Fd, Ed] -> grid (Ed/64, Fd/64))
    transpose_fast<true><<<dim3(Ed/64, Fd/64, 1), tb>>>(Wo, wot, Fd, Ed, 0, 0);
    // 5: vt = Wv^T @ x^T + bv (per batch) -> [E, S]; gx=4, gy=4, gz=8 -> T=128
    tc_gemm<0, true, true><<<gg, gt, SMEM_TOTAL>>>(
        wt + 2 * EE, xr, bv, nullptr, vt, Ed, Sd, 1.0f, 0, SE, SE, 0, 128, 4, 16);
    // 6: scores = q @ k^T / 32; gx=4, gy=4, gz=8 -> T=128
    tc_gemm<0, false, false><<<gg, gt, SMEM_TOTAL>>>(
        q, k, nullptr, nullptr, at, Ed, Sd, 0.03125f, SE, SE, SS, 0, 128, 4, 16);
    // 7: softmax (RNA-rounded)
    softmax_kernel<<<Bd * Sd, tb>>>(at);
    // 8: attn_out = attn_w @ v; gx=4, gy=4, gz=8 -> T=128
    tc_gemm<0, true, false><<<gg, gt, SMEM_TOTAL>>>(
        at, vt, nullptr, nullptr, ao, Sd, Ed, 1.0f, SS, SE, SE, 0, 128, 4, 16);
    // 9-10: Wd GEMM (+bias +resid x) then LN1; gx=4, gy=32 -> T=128
    tc_gemm<0, false, false><<<gg, gt, SMEM_TOTAL>>>(
        ao, wdt, bd, x, tmp, Ed, Ed, 1.0f, 0, 0, 0, 0, 128, 4, 128);
    ln_kernel<true><<<MTOT, tb>>>(tmp, g1, b1, h1);
    // 11: ff = gelu(h1 @ Wi + bi); gx=16, gy=32 -> T=512
    tc_gemm<1, true, false><<<gg, gt, SMEM_TOTAL>>>(
        h1, wit, bi, nullptr, ff, Ed, Fd, 1.0f, 0, 0, 0, 0, 512, 16, 512);
    // 12-13: out = LN(ff @ Wo + bo + h1); gx=4, gy=32 -> T=128 (K=4096 -> nk=128)
    tc_gemm<0, false, false><<<gg, gt, SMEM_TOTAL>>>(
        ff, wot, bo, h1, tmp, Fd, Ed, 1.0f, 0, 0, 0, 0, 128, 4, 128);
    ln_kernel<false><<<MTOT, tb>>>(tmp, g2, b2, out);
}

// round 10
// speedup vs baseline: 1.9903x; 1.0379x over previous
#include <cuda_runtime.h>
#include <math.h>
#include <stdint.h>

#if defined(__CUDA_ARCH_FEAT_SM103_ALL) || defined(__CUDA_ARCH_FEAT_SM100_ALL) || defined(__CUDA_ARCH_FEAT_SM101_ALL) || defined(__CUDA_ARCH_FEAT_SM110_ALL)
#define HAS_TC 1
#else
#define HAS_TC 0
#endif

// Problem dims
constexpr int Bd = 8;
constexpr int Sd = 1024;
constexpr int Ed = 1024;
constexpr int Fd = 4096;
constexpr int MTOT = Bd * Sd;   // 8192

// tcgen05 GEMM tile config: 256x256 tile = 2 x (128x256) MMA into TMEM halves
constexpr int TMM = 256;
constexpr int TN = 256;
constexpr int TK = 32;          // K elems per stage (128B per row)
constexpr int NS = 3;           // pipeline stages
constexpr int STAGE_BYTES = (TMM + TN) * 128;           // 65536
constexpr int SMEM_TOTAL = 1024 + NS * STAGE_BYTES;     // 197632
constexpr int NTHREADS = 288;   // 4 producer warps + 4 epilogue warps + 1 MMA warp
constexpr int GRID = 128;       // persistent CTAs

// idesc: c=F32(1), a=TF32(2), b=TF32(2), K-major both, N=256, M=128 (per dispatch)
constexpr uint32_t IDESC =
    (1u << 4) | (2u << 7) | (2u << 10) | ((TN / 8) << 17) | ((128 / 16) << 24);

#define OFF_TMEM   0
#define OFF_FULL(s)  (8 + 8*(s))
#define OFF_EMPTY(s) (8 + 8*NS + 8*(s))
#define OFF_FIN      (8 + 16*NS)
#define OFF_TFREE    (8 + 16*NS + 8)

// ---------------- scratch (device globals) ---------------------------------
__device__ float g_xr  [(long long)MTOT * Ed];
__device__ float g_qk  [(long long)2 * MTOT * Ed];   // q | k contiguous
__device__ float g_vt  [(long long)MTOT * Ed];       // V transposed [E,S] per batch
__device__ float g_at  [(long long)Bd * Sd * Sd];
__device__ float g_ao  [(long long)MTOT * Ed];
__device__ float g_tmp [(long long)MTOT * Ed];
__device__ float g_h1  [(long long)MTOT * Ed];
__device__ float g_ff  [(long long)MTOT * Fd];
__device__ float g_wt  [(long long)3 * Ed * Ed];     // Wq^T | Wk^T | Wv^T
__device__ float g_b2  [2 * Ed];
__device__ float g_wdt [(long long)Ed * Ed];
__device__ float g_wit [(long long)Fd * Ed];
__device__ float g_wot [(long long)Ed * Fd];

// ---------------- PTX helpers -------------------------------------------------
__device__ __forceinline__ uint32_t smem_u32(const void* p) {
    uint32_t a;
    asm("{ .reg .u64 t; cvta.to.shared.u64 t, %1; cvt.u32.u64 %0, t; }" : "=r"(a) : "l"(p));
    return a;
}
__device__ __forceinline__ uint32_t elect_one() {
    uint32_t p;
    asm volatile("{ .reg .pred p; elect.sync _|p, 0xFFFFFFFF; selp.b32 %0,1,0,p; }" : "=r"(p));
    return p;
}
__device__ __forceinline__ void mbar_init(uint32_t a, uint32_t c) {
    asm volatile("mbarrier.init.shared.b64 [%0], %1;" :: "r"(a), "r"(c) : "memory");
}
__device__ __forceinline__ void mbar_arrive(uint32_t a) {
    asm volatile("mbarrier.arrive.shared.b64 _, [%0];" :: "r"(a) : "memory");
}
__device__ __forceinline__ void mbar_wait(uint32_t a, uint32_t ph) {
    uint32_t done;
    asm volatile(
        "{\n\t.reg .pred p;\n\t"
        "mbarrier.try_wait.parity.acquire.cta.shared::cta.b64 p, [%1], %2;\n\t"
        "selp.b32 %0, 1, 0, p;\n\t}"
        : "=r"(done) : "r"(a), "r"(ph) : "memory");
    if (!done) {
        asm volatile(
            "{\n\t.reg .pred P1;\n\t"
            "WL%=:\n\t"
            "mbarrier.try_wait.parity.acquire.cta.shared::cta.b64 P1, [%0], %1, 0x989680;\n\t"
            "@P1 bra.uni WD%=;\n\t"
            "bra.uni WL%=;\n\t"
            "WD%=:\n\t}"
            :: "r"(a), "r"(ph) : "memory");
    }
}
__device__ __forceinline__ void cp16(uint32_t dst, const void* src) {
    asm volatile("cp.async.cg.shared.global [%0], [%1], 16;" :: "r"(dst), "l"(src) : "memory");
}
__device__ __forceinline__ void cpasync_arrive(uint32_t a) {
    asm volatile("cp.async.mbarrier.arrive.noinc.shared::cta.b64 [%0];" :: "r"(a) : "memory");
}
__device__ __forceinline__ uint64_t make_desc(uint32_t addr) {
    return 0x4000404000010000ULL | ((uint64_t)(addr >> 4) & 0x3FFF);
}
__device__ __forceinline__ float rna_tf32(float x) {
    uint32_t u;
    asm("cvt.rna.tf32.f32 %0, %1;" : "=r"(u) : "f"(x));
    return __uint_as_float(u);
}

#if HAS_TC
__device__ __forceinline__ void mma_tf32(uint32_t d, uint64_t ad, uint64_t bd,
                                         uint32_t idesc, uint32_t en) {
    asm volatile(
        "{\n\t.reg .pred p;\n\t"
        "setp.ne.u32 p, %4, 0;\n\t"
        "tcgen05.mma.cta_group::1.kind::tf32 [%0], %1, %2, %3, {%5, %5, %5, %5}, p;\n\t}"
        :: "r"(d), "l"(ad), "l"(bd), "r"(idesc), "r"(en), "r"(0u)
        : "memory");
}
#define TC_ALLOC(sa, n)   asm volatile("tcgen05.alloc.cta_group::1.sync.aligned.shared::cta.b32 [%0], %1;" :: "r"(sa), "r"(n) : "memory")
#define TC_DEALLOC(t, n)  asm volatile("tcgen05.dealloc.cta_group::1.sync.aligned.b32 %0, %1;" :: "r"(t), "r"(n))
#define TC_RELINQ()       asm volatile("tcgen05.relinquish_alloc_permit.cta_group::1.sync.aligned;")
#define TC_COMMIT(mb)     asm volatile("tcgen05.commit.cta_group::1.mbarrier::arrive::one.shared::cluster.b64 [%0];" :: "r"(mb) : "memory")
#define TC_FENCE_AFTER()  asm volatile("tcgen05.fence::after_thread_sync;" ::: "memory")
#define TC_FENCE_BEFORE() asm volatile("tcgen05.fence::before_thread_sync;" ::: "memory")
#define TC_WAIT_LD()      asm volatile("tcgen05.wait::ld.sync.aligned;" ::: "memory")

#define LDTM_X32(r, ta) \
    asm volatile( \
        "tcgen05.ld.sync.aligned.32x32b.x32.b32 " \
        "{%0, %1, %2, %3, %4, %5, %6, %7, " \
        " %8, %9, %10, %11, %12, %13, %14, %15, " \
        " %16, %17, %18, %19, %20, %21, %22, %23, " \
        " %24, %25, %26, %27, %28, %29, %30, %31}, [%32];" \
        : "=r"((r)[0]),  "=r"((r)[1]),  "=r"((r)[2]),  "=r"((r)[3]), \
          "=r"((r)[4]),  "=r"((r)[5]),  "=r"((r)[6]),  "=r"((r)[7]), \
          "=r"((r)[8]),  "=r"((r)[9]),  "=r"((r)[10]), "=r"((r)[11]), \
          "=r"((r)[12]), "=r"((r)[13]), "=r"((r)[14]), "=r"((r)[15]), \
          "=r"((r)[16]), "=r"((r)[17]), "=r"((r)[18]), "=r"((r)[19]), \
          "=r"((r)[20]), "=r"((r)[21]), "=r"((r)[22]), "=r"((r)[23]), \
          "=r"((r)[24]), "=r"((r)[25]), "=r"((r)[26]), "=r"((r)[27]), \
          "=r"((r)[28]), "=r"((r)[29]), "=r"((r)[30]), "=r"((r)[31]) \
        : "r"(ta))
#endif // HAS_TC

// ---------------- persistent warp-specialized tcgen05 TF32 GEMM ----------------
// (unchanged from R9 — proven) C = act(alpha*A@Bt^T + bias + resid).
template<int ACT, bool ROUND, bool BROW>
__global__ void __launch_bounds__(NTHREADS, 1)
tc_gemm(const float* __restrict__ A, const float* __restrict__ Bt,
        const float* __restrict__ bias, const float* __restrict__ resid,
        float* __restrict__ C, int K, int N, float alpha,
        long long sA, long long sB, long long sC, long long sBias,
        int T, int gx, int gxy)
{
#if HAS_TC
    extern __shared__ char smem[];
    const uint32_t sb = smem_u32(smem);
    const int tid = threadIdx.x;
    const int wid = tid >> 5;
    const int nk = K / TK;

    if (tid == 0) {
        for (int s = 0; s < NS; s++) {
            mbar_init(sb + OFF_FULL(s), 128);
            mbar_init(sb + OFF_EMPTY(s), 1);
        }
        mbar_init(sb + OFF_FIN, 1);
        mbar_init(sb + OFF_TFREE, 128);
    }
    if (wid == 8) {
        TC_ALLOC(sb + OFF_TMEM, 512);
        TC_RELINQ();
    }
    __syncthreads();
    uint32_t tmem;
    asm volatile("ld.shared.b32 %0, [%1];" : "=r"(tmem) : "r"(sb + OFF_TMEM));

    if (tid < 128) {
        const int a = tid >> 3;
        const int c = tid & 7;
        uint32_t o0 = (uint32_t)(a * 128 + c * 16);
        const uint32_t swz = o0 ^ ((o0 >> 3) & 0x70);
        const long long str16 = 16LL * K;

        int s = 0; uint32_t eph = 1;
        for (int t = blockIdx.x; t < T; t += GRID) {
            const int tz = t / gxy;
            const int rem = t - tz * gxy;
            const int ty = rem / gx;
            const int tx = rem - ty * gx;
            const float* pA = A  + (long long)tz * sA + (long long)(ty * TMM + a) * K + c * 4;
            const float* pB = Bt + (long long)tz * sB + (long long)(tx * TN  + a) * K + c * 4;
            for (int kt = 0; kt < nk; kt++) {
                mbar_wait(sb + OFF_EMPTY(s), eph);
                const uint32_t st = sb + 1024 + s * STAGE_BYTES;
                #pragma unroll
                for (int m = 0; m < 16; m++)
                    cp16(st + swz + m * 2048, pA + m * str16);
                #pragma unroll
                for (int m = 0; m < 16; m++)
                    cp16(st + swz + 32768 + m * 2048, pB + m * str16);
                cpasync_arrive(sb + OFF_FULL(s));
                pA += TK; pB += TK;
                if (++s == NS) { s = 0; eph ^= 1; }
            }
        }
    } else if (tid < 256) {
        const int lane = tid & 31;
        const int sp = wid & 3;
        int n = 0;
        for (int t = blockIdx.x; t < T; t += GRID, n++) {
            mbar_wait(sb + OFF_FIN, n & 1);
            TC_FENCE_AFTER();
            const int tz = t / gxy;
            const int rem = t - tz * gxy;
            const int ty = rem / gx;
            const int tx = rem - ty * gx;
            const int bm = ty * TMM, bn = tx * TN;
            const float* biasz = bias ? bias + (long long)tz * sBias : nullptr;

            #pragma unroll 1
            for (int h = 0; h < 2; h++) {
                const long long row = bm + h * 128 + sp * 32 + lane;
                float* crow = C + (long long)tz * sC + row * (long long)N + bn;
                const float* rrow = resid ? resid + (long long)tz * sC + row * (long long)N + bn
                                          : nullptr;
                float brow = 0.0f;
                if (BROW && biasz) brow = biasz[row];
                const uint32_t tmh = tmem + h * 256;

                #pragma unroll 1
                for (int cb = 0; cb < 8; cb++) {
                    uint32_t r[32];
                    LDTM_X32(r, tmh + cb * 32);
                    TC_WAIT_LD();
                    float v[32];
                    #pragma unroll
                    for (int j = 0; j < 32; j++) v[j] = __uint_as_float(r[j]) * alpha;
                    if (biasz) {
                        if (BROW) {
                            #pragma unroll
                            for (int j = 0; j < 32; j++) v[j] += brow;
                        } else {
                            #pragma unroll
                            for (int j0 = 0; j0 < 32; j0 += 4) {
                                float4 bb = *reinterpret_cast<const float4*>(biasz + bn + cb * 32 + j0);
                                v[j0+0] += bb.x; v[j0+1] += bb.y; v[j0+2] += bb.z; v[j0+3] += bb.w;
                            }
                        }
                    }
                    if (rrow) {
                        #pragma unroll
                        for (int j0 = 0; j0 < 32; j0 += 4) {
                            float4 rv = *reinterpret_cast<const float4*>(rrow + cb * 32 + j0);
                            v[j0+0] += rv.x; v[j0+1] += rv.y; v[j0+2] += rv.z; v[j0+3] += rv.w;
                        }
                    }
                    if constexpr (ACT == 1) {
                        #pragma unroll
                        for (int j = 0; j < 32; j++)
                            v[j] = 0.5f * v[j] * (1.0f + erff(v[j] * 0.70710678118654752f));
                    }
                    if constexpr (ROUND) {
                        #pragma unroll
                        for (int j = 0; j < 32; j++) v[j] = rna_tf32(v[j]);
                    }
                    #pragma unroll
                    for (int j0 = 0; j0 < 32; j0 += 4) {
                        float4 o; o.x = v[j0]; o.y = v[j0+1]; o.z = v[j0+2]; o.w = v[j0+3];
                        *reinterpret_cast<float4*>(crow + cb * 32 + j0) = o;
                    }
                }
            }
            TC_FENCE_BEFORE();
            mbar_arrive(sb + OFF_TFREE);
        }
    } else {
        uint32_t ep = elect_one();
        int s = 0; uint32_t ph = 0; int n = 0;
        for (int t = blockIdx.x; t < T; t += GRID, n++) {
            mbar_wait(sb + OFF_TFREE, (n + 1) & 1);
            TC_FENCE_AFTER();
            for (int kt = 0; kt < nk; kt++) {
                mbar_wait(sb + OFF_FULL(s), ph);
                if (ep) {
                    const uint32_t st = sb + 1024 + s * STAGE_BYTES;
                    uint64_t ad0 = make_desc(st);
                    uint64_t ad1 = make_desc(st + 16384);
                    uint64_t bd  = make_desc(st + 32768);
                    const uint32_t en0 = (uint32_t)(kt != 0);
                    #pragma unroll
                    for (int j = 0; j < 4; j++) {
                        const uint32_t en = en0 | (uint32_t)(j != 0);
                        mma_tf32(tmem,       ad0 + 2 * j, bd + 2 * j, IDESC, en);
                        mma_tf32(tmem + 256, ad1 + 2 * j, bd + 2 * j, IDESC, en);
                    }
                    TC_COMMIT(sb + OFF_EMPTY(s));
                    if (kt == nk - 1) TC_COMMIT(sb + OFF_FIN);
                }
                if (++s == NS) { s = 0; ph ^= 1; }
            }
        }
    }

    __syncthreads();
    if (wid == 8) TC_DEALLOC(tmem, 512);
#endif // HAS_TC
}

// ---------------- merged QKV GEMM: QK projections (256 tiles) + V^T (128 tiles) --
// All tiles: K=1024, N=1024 row stride, alpha=1, TMM x TN. T = 384, 3 tiles/CTA.
// t < 256:  QK  tz=t>>7 (0=Q,1=K): A=xr[ty], B=wt[tz]+tx, C=qk[tz], col bias b2qk[tz]
// t >= 256: V^T tz=(t-256)>>4 (batch): A=wvT[ty], B=xr[batch]+tx, C=vt[batch], row bias bv
struct QkvTile {
    const float* pA; const float* pB; float* pC;
    const float* bias; int browMode; int bm; int bn;
};
__device__ __forceinline__ QkvTile qkv_tile(int t, const float* xr, const float* wt,
                                            const float* b2qk, const float* bv,
                                            float* qk, float* vt)
{
    QkvTile d;
    const long long ME = (long long)MTOT * Ed;
    const long long SE = (long long)Sd * Ed;
    const long long EE = (long long)Ed * Ed;
    if (t < 256) {
        const int tz = t >> 7, r = t & 127, ty = r >> 2, tx = r & 3;
        d.pA = xr + (long long)ty * TMM * Ed;
        d.pB = wt + tz * EE + (long long)tx * TN * Ed;
        d.pC = qk + tz * ME;
        d.bias = b2qk + tz * Ed;
        d.browMode = 0;
        d.bm = ty * TMM; d.bn = tx * TN;
    } else {
        const int u = t - 256, tz = u >> 4, r = u & 15, ty = r >> 2, tx = r & 3;
        d.pA = wt + 2 * EE + (long long)ty * TMM * Ed;
        d.pB = xr + tz * SE + (long long)tx * TN * Ed;
        d.pC = vt + tz * SE;
        d.bias = bv;
        d.browMode = 1;
        d.bm = ty * TMM; d.bn = tx * TN;
    }
    return d;
}

__global__ void __launch_bounds__(NTHREADS, 1)
tc_gemm_qkv(const float* __restrict__ xr, const float* __restrict__ wt,
            const float* __restrict__ b2qk, const float* __restrict__ bv,
            float* __restrict__ qk, float* __restrict__ vt)
{
#if HAS_TC
    extern __shared__ char smem[];
    const uint32_t sb = smem_u32(smem);
    const int tid = threadIdx.x;
    const int wid = tid >> 5;
    const int K = Ed, N = Ed, nk = Ed / TK;
    const int T = 384;

    if (tid == 0) {
        for (int s = 0; s < NS; s++) {
            mbar_init(sb + OFF_FULL(s), 128);
            mbar_init(sb + OFF_EMPTY(s), 1);
        }
        mbar_init(sb + OFF_FIN, 1);
        mbar_init(sb + OFF_TFREE, 128);
    }
    if (wid == 8) {
        TC_ALLOC(sb + OFF_TMEM, 512);
        TC_RELINQ();
    }
    __syncthreads();
    uint32_t tmem;
    asm volatile("ld.shared.b32 %0, [%1];" : "=r"(tmem) : "r"(sb + OFF_TMEM));

    if (tid < 128) {
        const int a = tid >> 3;
        const int c = tid & 7;
        uint32_t o0 = (uint32_t)(a * 128 + c * 16);
        const uint32_t swz = o0 ^ ((o0 >> 3) & 0x70);
        const long long str16 = 16LL * K;

        int s = 0; uint32_t eph = 1;
        for (int t = blockIdx.x; t < T; t += GRID) {
            QkvTile d = qkv_tile(t, xr, wt, b2qk, bv, qk, vt);
            const float* pA = d.pA + (long long)a * K + c * 4;
            const float* pB = d.pB + (long long)a * K + c * 4;
            for (int kt = 0; kt < nk; kt++) {
                mbar_wait(sb + OFF_EMPTY(s), eph);
                const uint32_t st = sb + 1024 + s * STAGE_BYTES;
                #pragma unroll
                for (int m = 0; m < 16; m++)
                    cp16(st + swz + m * 2048, pA + m * str16);
                #pragma unroll
                for (int m = 0; m < 16; m++)
                    cp16(st + swz + 32768 + m * 2048, pB + m * str16);
                cpasync_arrive(sb + OFF_FULL(s));
                pA += TK; pB += TK;
                if (++s == NS) { s = 0; eph ^= 1; }
            }
        }
    } else if (tid < 256) {
        const int lane = tid & 31;
        const int sp = wid & 3;
        int n = 0;
        for (int t = blockIdx.x; t < T; t += GRID, n++) {
            mbar_wait(sb + OFF_FIN, n & 1);
            TC_FENCE_AFTER();
            QkvTile d = qkv_tile(t, xr, wt, b2qk, bv, qk, vt);

            #pragma unroll 1
            for (int h = 0; h < 2; h++) {
                const long long lrow = h * 128 + sp * 32 + lane;   // row within tile
                float* crow = d.pC + (d.bm + lrow) * (long long)N + d.bn;
                float brow = 0.0f;
                if (d.browMode) brow = d.bias[d.bm + lrow];
                const uint32_t tmh = tmem + h * 256;

                #pragma unroll 1
                for (int cb = 0; cb < 8; cb++) {
                    uint32_t r[32];
                    LDTM_X32(r, tmh + cb * 32);
                    TC_WAIT_LD();
                    float v[32];
                    #pragma unroll
                    for (int j = 0; j < 32; j++) v[j] = __uint_as_float(r[j]);
                    if (d.browMode) {
                        #pragma unroll
                        for (int j = 0; j < 32; j++) v[j] += brow;
                    } else {
                        #pragma unroll
                        for (int j0 = 0; j0 < 32; j0 += 4) {
                            float4 bb = *reinterpret_cast<const float4*>(d.bias + d.bn + cb * 32 + j0);
                            v[j0+0] += bb.x; v[j0+1] += bb.y; v[j0+2] += bb.z; v[j0+3] += bb.w;
                        }
                    }
                    #pragma unroll
                    for (int j = 0; j < 32; j++) v[j] = rna_tf32(v[j]);
                    #pragma unroll
                    for (int j0 = 0; j0 < 32; j0 += 4) {
                        float4 o; o.x = v[j0]; o.y = v[j0+1]; o.z = v[j0+2]; o.w = v[j0+3];
                        *reinterpret_cast<float4*>(crow + cb * 32 + j0) = o;
                    }
                }
            }
            TC_FENCE_BEFORE();
            mbar_arrive(sb + OFF_TFREE);
        }
    } else {
        uint32_t ep = elect_one();
        int s = 0; uint32_t ph = 0; int n = 0;
        for (int t = blockIdx.x; t < T; t += GRID, n++) {
            mbar_wait(sb + OFF_TFREE, (n + 1) & 1);
            TC_FENCE_AFTER();
            for (int kt = 0; kt < nk; kt++) {
                mbar_wait(sb + OFF_FULL(s), ph);
                if (ep) {
                    const uint32_t st = sb + 1024 + s * STAGE_BYTES;
                    uint64_t ad0 = make_desc(st);
                    uint64_t ad1 = make_desc(st + 16384);
                    uint64_t bd  = make_desc(st + 32768);
                    const uint32_t en0 = (uint32_t)(kt != 0);
                    #pragma unroll
                    for (int j = 0; j < 4; j++) {
                        const uint32_t en = en0 | (uint32_t)(j != 0);
                        mma_tf32(tmem,       ad0 + 2 * j, bd + 2 * j, IDESC, en);
                        mma_tf32(tmem + 256, ad1 + 2 * j, bd + 2 * j, IDESC, en);
                    }
                    TC_COMMIT(sb + OFF_EMPTY(s));
                    if (kt == nk - 1) TC_COMMIT(sb + OFF_FIN);
                }
                if (++s == NS) { s = 0; ph ^= 1; }
            }
        }
    }

    __syncthreads();
    if (wid == 8) TC_DEALLOC(tmem, 512);
#endif // HAS_TC
}

// ---------------- elementwise kernels ---------------------------------------
__device__ __forceinline__ float block_sum(float v, float* sh) {
    const int lane = threadIdx.x & 31, w = threadIdx.x >> 5;
    #pragma unroll
    for (int o = 16; o; o >>= 1) v += __shfl_xor_sync(0xffffffffu, v, o);
    __syncthreads();
    if (lane == 0) sh[w] = v;
    __syncthreads();
    float s = 0.f;
    #pragma unroll
    for (int i = 0; i < 8; i++) s += sh[i];
    return s;
}
__device__ __forceinline__ float block_max(float v, float* sh) {
    const int lane = threadIdx.x & 31, w = threadIdx.x >> 5;
    #pragma unroll
    for (int o = 16; o; o >>= 1) v = fmaxf(v, __shfl_xor_sync(0xffffffffu, v, o));
    __syncthreads();
    if (lane == 0) sh[w] = v;
    __syncthreads();
    float s = -INFINITY;
    #pragma unroll
    for (int i = 0; i < 8; i++) s = fmaxf(s, sh[i]);
    return s;
}

__global__ void __launch_bounds__(256) softmax_kernel(float* __restrict__ data)
{
    __shared__ float sh[8];
    const long long row = blockIdx.x;
    float4* p = reinterpret_cast<float4*>(data + row * 1024);
    float4 x = p[threadIdx.x];
    float m = fmaxf(fmaxf(x.x, x.y), fmaxf(x.z, x.w));
    m = block_max(m, sh);
    x.x = expf(x.x - m); x.y = expf(x.y - m);
    x.z = expf(x.z - m); x.w = expf(x.w - m);
    float s = x.x + x.y + x.z + x.w;
    s = block_sum(s, sh);
    const float inv = 1.0f / s;
    x.x = rna_tf32(x.x * inv); x.y = rna_tf32(x.y * inv);
    x.z = rna_tf32(x.z * inv); x.w = rna_tf32(x.w * inv);
    p[threadIdx.x] = x;
}

template<bool ROUND>
__global__ void __launch_bounds__(256)
ln_kernel(const float* __restrict__ in, const float* __restrict__ g,
          const float* __restrict__ b, float* __restrict__ out)
{
    __shared__ float sh[8];
    const long long row = blockIdx.x;
    const float4* p = reinterpret_cast<const float4*>(in + row * 1024);
    float4 x = p[threadIdx.x];
    float s = x.x + x.y + x.z + x.w;
    s = block_sum(s, sh);
    const float mu = s * (1.0f / 1024.0f);
    const float dx = x.x - mu, dy = x.y - mu, dz = x.z - mu, dw = x.w - mu;
    float ss = dx * dx + dy * dy + dz * dz + dw * dw;
    ss = block_sum(ss, sh);
    const float rstd = rsqrtf(ss * (1.0f / 1024.0f) + 1e-12f);
    const float4 gg = reinterpret_cast<const float4*>(g)[threadIdx.x];
    const float4 bb = reinterpret_cast<const float4*>(b)[threadIdx.x];
    float4 o;
    o.x = dx * rstd * gg.x + bb.x;
    o.y = dy * rstd * gg.y + bb.y;
    o.z = dz * rstd * gg.z + bb.z;
    o.w = dw * rstd * gg.w + bb.w;
    if (ROUND) { o.x = rna_tf32(o.x); o.y = rna_tf32(o.y); o.z = rna_tf32(o.z); o.w = rna_tf32(o.w); }
    reinterpret_cast<float4*>(out + row * 1024)[threadIdx.x] = o;
}

// Fast 64x64 transpose body.
__device__ __forceinline__ void transpose_body(const float* __restrict__ in,
                                               float* __restrict__ out,
                                               int R, int C, int r0, int c0)
{
    __shared__ float t[64][65];
    const int fc = (threadIdx.x & 15) * 4;
    const int fr = threadIdx.x >> 4;

    #pragma unroll
    for (int i = 0; i < 4; i++) {
        const int r = fr + i * 16;
        float4 x = *reinterpret_cast<const float4*>(in + (long long)(r0 + r) * C + c0 + fc);
        t[fc + 0][r] = x.x; t[fc + 1][r] = x.y; t[fc + 2][r] = x.z; t[fc + 3][r] = x.w;
    }
    __syncthreads();
    #pragma unroll
    for (int i = 0; i < 4; i++) {
        const int oc = fr + i * 16;
        float4 y;
        y.x = rna_tf32(t[oc][fc + 0]); y.y = rna_tf32(t[oc][fc + 1]);
        y.z = rna_tf32(t[oc][fc + 2]); y.w = rna_tf32(t[oc][fc + 3]);
        *reinterpret_cast<float4*>(out + (long long)(c0 + oc) * R + r0 + fc) = y;
    }
}

// Prep 1: blocks [0,1024): grid-stride RNA-round of x into xr.
//         blocks 1024,1025: copy bq/bk into b2.
//         blocks [1026, 1026+1024): transpose Wq/Wk/Wv/Wd (1024x1024 each, 256 blocks each).
__global__ void __launch_bounds__(256)
prep1_kernel(const float4* __restrict__ x, float4* __restrict__ xr, long long n4,
             const float4* __restrict__ bq, const float4* __restrict__ bk, float4* __restrict__ b2,
             const float* __restrict__ Wq, const float* __restrict__ Wk,
             const float* __restrict__ Wv, const float* __restrict__ Wd,
             float* __restrict__ oq, float* __restrict__ ok,
             float* __restrict__ ov, float* __restrict__ od)
{
    const int b = blockIdx.x;
    if (b < 1024) {
        for (long long i = b * 256LL + threadIdx.x; i < n4; i += 1024LL * 256LL) {
            float4 v = x[i];
            v.x = rna_tf32(v.x); v.y = rna_tf32(v.y);
            v.z = rna_tf32(v.z); v.w = rna_tf32(v.w);
            xr[i] = v;
        }
    } else if (b < 1026) {
        const float4* src = (b == 1024) ? bq : bk;
        b2[(b - 1024) * 256 + threadIdx.x] = src[threadIdx.x];
    } else {
        const int idx = b - 1026;                 // 0..1023
        const int w = idx >> 8;                   // which weight
        const int r = (idx & 255) >> 4;           // 0..15
        const int c = idx & 15;                   // 0..15
        const float* in = w == 0 ? Wq : w == 1 ? Wk : w == 2 ? Wv : Wd;
        float* out      = w == 0 ? oq : w == 1 ? ok : w == 2 ? ov : od;
        transpose_body(in, out, 1024, 1024, r * 64, c * 64);
    }
}

// Prep 2: blocks [0,1024): transpose Wi [Ed,Fd] -> wit [Fd,Ed]  (cx 0..63, ry 0..15)
//         blocks [1024, 2048): transpose Wo [Fd,Ed] -> wot [Ed,Fd] (cx 0..15, ry 0..63)
__global__ void __launch_bounds__(256)
prep2_kernel(const float* __restrict__ Wi, float* __restrict__ wit,
             const float* __restrict__ Wo, float* __restrict__ wot)
{
    const int b = blockIdx.x;
    if (b < 1024) {
        const int cx = b & 63, ry = b >> 6;       // Fd/64=64 cols, Ed/64=16 rows
        transpose_body(Wi, wit, Ed, Fd, ry * 64, cx * 64);
    } else {
        const int idx = b - 1024;
        const int cx = idx & 15, ry = idx >> 4;   // Ed/64=16 cols, Fd/64=64 rows
        transpose_body(Wo, wot, Fd, Ed, ry * 64, cx * 64);
    }
}

// ---------------- host launcher -----------------------------------------------
extern "C" void kernel_launch(void* const* d_in, const int* in_sizes, int n_in,
                              void* d_out, int out_size)
{
    const float* x  = (const float*)d_in[0];
    const float* Wq = (const float*)d_in[1];
    const float* bq = (const float*)d_in[2];
    const float* Wk = (const float*)d_in[3];
    const float* bk = (const float*)d_in[4];
    const float* Wv = (const float*)d_in[5];
    const float* bv = (const float*)d_in[6];
    const float* Wd = (const float*)d_in[7];
    const float* bd = (const float*)d_in[8];
    const float* g1 = (const float*)d_in[9];
    const float* b1 = (const float*)d_in[10];
    const float* Wi = (const float*)d_in[11];
    const float* bi = (const float*)d_in[12];
    const float* Wo = (const float*)d_in[13];
    const float* bo = (const float*)d_in[14];
    const float* g2 = (const float*)d_in[15];
    const float* b2 = (const float*)d_in[16];
    float* out = (float*)d_out;

    float *xr, *qk, *vt, *at, *ao, *tmp, *h1, *ff;
    float *wt, *b2qk, *wdt, *wit, *wot;
    cudaGetSymbolAddress((void**)&xr,   g_xr);
    cudaGetSymbolAddress((void**)&qk,   g_qk);
    cudaGetSymbolAddress((void**)&vt,   g_vt);
    cudaGetSymbolAddress((void**)&at,   g_at);
    cudaGetSymbolAddress((void**)&ao,   g_ao);
    cudaGetSymbolAddress((void**)&tmp,  g_tmp);
    cudaGetSymbolAddress((void**)&h1,   g_h1);
    cudaGetSymbolAddress((void**)&ff,   g_ff);
    cudaGetSymbolAddress((void**)&wt,   g_wt);
    cudaGetSymbolAddress((void**)&b2qk, g_b2);
    cudaGetSymbolAddress((void**)&wdt,  g_wdt);
    cudaGetSymbolAddress((void**)&wit,  g_wit);
    cudaGetSymbolAddress((void**)&wot,  g_wot);

    cudaFuncSetAttribute(tc_gemm_qkv,              cudaFuncAttributeMaxDynamicSharedMemorySize, SMEM_TOTAL);
    cudaFuncSetAttribute(tc_gemm<0, true,  false>, cudaFuncAttributeMaxDynamicSharedMemorySize, SMEM_TOTAL);
    cudaFuncSetAttribute(tc_gemm<0, false, false>, cudaFuncAttributeMaxDynamicSharedMemorySize, SMEM_TOTAL);
    cudaFuncSetAttribute(tc_gemm<1, true,  false>, cudaFuncAttributeMaxDynamicSharedMemorySize, SMEM_TOTAL);

    const long long ME = (long long)MTOT * Ed;
    const long long SE = (long long)Sd * Ed;
    const long long SS = (long long)Sd * Sd;
    const long long EE = (long long)Ed * Ed;
    float* q = qk;
    float* k = qk + ME;
    const dim3 tb(256);
    const dim3 gt(NTHREADS);
    const dim3 gg(GRID);

    // 0: prep1 (round x + bias concat + 4x 1024^2 transposes)
    prep1_kernel<<<2050, tb>>>((const float4*)x, (float4*)xr, ME / 4,
                               (const float4*)bq, (const float4*)bk, (float4*)b2qk,
                               Wq, Wk, Wv, Wd, wt, wt + EE, wt + 2 * EE, wdt);
    // 1: prep2 (Wi + Wo transposes)
    prep2_kernel<<<2048, tb>>>(Wi, wit, Wo, wot);
    // 2: merged QKV (Q, K projections + V^T), T=384
    tc_gemm_qkv<<<gg, gt, SMEM_TOTAL>>>(xr, wt, b2qk, bv, qk, vt);
    // 3: scores = q @ k^T / 32  <-- profiled launch (harness offset 2 => ncu -s 5)
    tc_gemm<0, false, false><<<gg, gt, SMEM_TOTAL>>>(
        q, k, nullptr, nullptr, at, Ed, Sd, 0.03125f, SE, SE, SS, 0, 128, 4, 16);
    // 4: softmax (RNA-rounded)
    softmax_kernel<<<Bd * Sd, tb>>>(at);
    // 5: attn_out = attn_w @ v (Bt = vt, [E,S] K-major)
    tc_gemm<0, true, false><<<gg, gt, SMEM_TOTAL>>>(
        at, vt, nullptr, nullptr, ao, Sd, Ed, 1.0f, SS, SE, SE, 0, 128, 4, 16);
    // 6-7: Wd GEMM (+bias +resid x) then LN1
    tc_gemm<0, false, false><<<gg, gt, SMEM_TOTAL>>>(
        ao, wdt, bd, x, tmp, Ed, Ed, 1.0f, 0, 0, 0, 0, 128, 4, 128);
    ln_kernel<true><<<MTOT, tb>>>(tmp, g1, b1, h1);
    // 8: ff = gelu(h1 @ Wi + bi); T=512
    tc_gemm<1, true, false><<<gg, gt, SMEM_TOTAL>>>(
        h1, wit, bi, nullptr, ff, Ed, Fd, 1.0f, 0, 0, 0, 0, 512, 16, 512);
    // 9-10: out = LN(ff @ Wo + bo + h1); K=4096
    tc_gemm<0, false, false><<<gg, gt, SMEM_TOTAL>>>(
        ff, wot, bo, h1, tmp, Fd, Ed, 1.0f, 0, 0, 0, 0, 128, 4, 128);
    ln_kernel<false><<<MTOT, tb>>>(tmp, g2, b2, out);
}